// round 1
// baseline (speedup 1.0000x reference)
#include <cuda_runtime.h>
#include <math.h>

#define NSEQ 512
#define CHN  128
#define HD   128
#define NROWS (NSEQ*NSEQ)   // 262144

// Scratch (__device__ globals: allocation-free per harness rules)
__device__ float g_xn[(size_t)NROWS * CHN];   // 134 MB, LN(x) row-major [row][c]
__device__ float g_a [(size_t)HD * NROWS];    // 134 MB, channel-major [d][i*512+k]
__device__ float g_b [(size_t)HD * NROWS];    // 134 MB, channel-major [d][j*512+k]
__device__ float g_t [(size_t)HD * NROWS];    // 134 MB, channel-major [d][i*512+j]

// ---------------------------------------------------------------------------
// K0: xn = LayerNorm(x) over C=128.  One warp per row, 8 rows per block.
// ---------------------------------------------------------------------------
__global__ void k0_ln(const float* __restrict__ x,
                      const float* __restrict__ w,
                      const float* __restrict__ b) {
    int row  = blockIdx.x * blockDim.y + threadIdx.y;
    int lane = threadIdx.x;                       // 0..31, 4 elems each
    const float* xr = x + (size_t)row * CHN;
    float4 v = *(const float4*)(xr + lane * 4);
    float s = v.x + v.y + v.z + v.w;
    float q = v.x*v.x + v.y*v.y + v.z*v.z + v.w*v.w;
    #pragma unroll
    for (int o = 16; o > 0; o >>= 1) {
        s += __shfl_xor_sync(0xffffffffu, s, o);
        q += __shfl_xor_sync(0xffffffffu, q, o);
    }
    float mean = s * (1.0f / CHN);
    float var  = q * (1.0f / CHN) - mean * mean;
    float rstd = rsqrtf(var + 1e-5f);
    float4 wv = *(const float4*)(w + lane * 4);
    float4 bv = *(const float4*)(b + lane * 4);
    float4 o;
    o.x = (v.x - mean) * rstd * wv.x + bv.x;
    o.y = (v.y - mean) * rstd * wv.y + bv.y;
    o.z = (v.z - mean) * rstd * wv.z + bv.z;
    o.w = (v.w - mean) * rstd * wv.w + bv.w;
    *(float4*)(g_xn + (size_t)row * CHN + lane * 4) = o;
}

// ---------------------------------------------------------------------------
// K1: h = (xn @ p_in_w^T) * sigmoid(xn @ g_in_w^T); split into a (ch<128) and
//     b (ch>=128), written CHANNEL-MAJOR:  g_a[d][row], g_b[d][row].
// Block: 64 rows x 64 channels, K=128 in 2 stages of 64. 256 threads, 4x4
// micro-tile with DUAL accumulators (p and g).
// ---------------------------------------------------------------------------
__global__ void __launch_bounds__(256)
k1_proj(const float* __restrict__ pw, const float* __restrict__ gw) {
    __shared__ float As[64][64];   // [k][row]
    __shared__ float Ps[64][64];   // [k][ch]
    __shared__ float Gs[64][64];   // [k][ch]
    int tid = threadIdx.x;
    int rowTile = blockIdx.x * 64;
    int chTile  = blockIdx.y * 64;   // 0,64,128,192 over 2H=256
    int tx = tid & 15, ty = tid >> 4;

    float accP[4][4] = {}, accG[4][4] = {};

    for (int k0 = 0; k0 < CHN; k0 += 64) {
        #pragma unroll
        for (int rep = 0; rep < 4; rep++) {
            int f   = tid + rep * 256;      // 0..1023
            int r   = f & 63;               // row / ch within tile
            int k4  = f >> 6;               // 0..15 (float4 index in k)
            float4 av = *(const float4*)(g_xn + (size_t)(rowTile + r) * CHN + k0 + k4 * 4);
            As[k4*4+0][r] = av.x; As[k4*4+1][r] = av.y;
            As[k4*4+2][r] = av.z; As[k4*4+3][r] = av.w;
            float4 pv = *(const float4*)(pw + (size_t)(chTile + r) * CHN + k0 + k4 * 4);
            Ps[k4*4+0][r] = pv.x; Ps[k4*4+1][r] = pv.y;
            Ps[k4*4+2][r] = pv.z; Ps[k4*4+3][r] = pv.w;
            float4 gv = *(const float4*)(gw + (size_t)(chTile + r) * CHN + k0 + k4 * 4);
            Gs[k4*4+0][r] = gv.x; Gs[k4*4+1][r] = gv.y;
            Gs[k4*4+2][r] = gv.z; Gs[k4*4+3][r] = gv.w;
        }
        __syncthreads();
        #pragma unroll 8
        for (int k = 0; k < 64; k++) {
            float4 a = *(const float4*)&As[k][tx * 4];
            float4 p = *(const float4*)&Ps[k][ty * 4];
            float4 g = *(const float4*)&Gs[k][ty * 4];
            float av[4] = {a.x, a.y, a.z, a.w};
            float pv[4] = {p.x, p.y, p.z, p.w};
            float gv[4] = {g.x, g.y, g.z, g.w};
            #pragma unroll
            for (int i = 0; i < 4; i++)
                #pragma unroll
                for (int j = 0; j < 4; j++) {
                    accP[i][j] += av[i] * pv[j];
                    accG[i][j] += av[i] * gv[j];
                }
        }
        __syncthreads();
    }

    bool isA   = (chTile < HD);
    float* dst = isA ? g_a : g_b;
    int dBase  = chTile - (isA ? 0 : HD) + ty * 4;
    int rowBase = rowTile + tx * 4;
    #pragma unroll
    for (int j = 0; j < 4; j++) {
        int d = dBase + j;
        float4 o;
        o.x = accP[0][j] / (1.0f + __expf(-accG[0][j]));
        o.y = accP[1][j] / (1.0f + __expf(-accG[1][j]));
        o.z = accP[2][j] / (1.0f + __expf(-accG[2][j]));
        o.w = accP[3][j] / (1.0f + __expf(-accG[3][j]));
        *(float4*)(dst + (size_t)d * NROWS + rowBase) = o;
    }
}

// ---------------------------------------------------------------------------
// K2: per-channel einsum  t[d][i][j] = sum_k a[d][i][k] * b[d][j][k]
// 128 independent 512x512x512 NT sgemms. Block: 64x64 tile, K stage 64.
// ---------------------------------------------------------------------------
__global__ void __launch_bounds__(256)
k2_einsum() {
    __shared__ float As[64][64];   // [k][i]
    __shared__ float Bs[64][64];   // [k][j]
    int tid = threadIdx.x;
    int d = blockIdx.z;
    int iTile = blockIdx.x * 64;
    int jTile = blockIdx.y * 64;
    const float* Ab = g_a + (size_t)d * NROWS;
    const float* Bb = g_b + (size_t)d * NROWS;
    int tx = tid & 15, ty = tid >> 4;
    float acc[4][4] = {};

    for (int k0 = 0; k0 < NSEQ; k0 += 64) {
        #pragma unroll
        for (int rep = 0; rep < 4; rep++) {
            int f  = tid + rep * 256;
            int r  = f & 63;
            int k4 = f >> 6;
            float4 av = *(const float4*)(Ab + (size_t)(iTile + r) * NSEQ + k0 + k4 * 4);
            As[k4*4+0][r] = av.x; As[k4*4+1][r] = av.y;
            As[k4*4+2][r] = av.z; As[k4*4+3][r] = av.w;
            float4 bv = *(const float4*)(Bb + (size_t)(jTile + r) * NSEQ + k0 + k4 * 4);
            Bs[k4*4+0][r] = bv.x; Bs[k4*4+1][r] = bv.y;
            Bs[k4*4+2][r] = bv.z; Bs[k4*4+3][r] = bv.w;
        }
        __syncthreads();
        #pragma unroll 8
        for (int k = 0; k < 64; k++) {
            float4 a = *(const float4*)&As[k][tx * 4];
            float4 b = *(const float4*)&Bs[k][ty * 4];
            float av[4] = {a.x, a.y, a.z, a.w};
            float bv[4] = {b.x, b.y, b.z, b.w};
            #pragma unroll
            for (int i = 0; i < 4; i++)
                #pragma unroll
                for (int j = 0; j < 4; j++)
                    acc[i][j] += av[i] * bv[j];
        }
        __syncthreads();
    }

    float* T = g_t + (size_t)d * NROWS;
    #pragma unroll
    for (int i = 0; i < 4; i++) {
        int irow = iTile + tx * 4 + i;
        float4 o = make_float4(acc[i][0], acc[i][1], acc[i][2], acc[i][3]);
        *(float4*)(T + (size_t)irow * NSEQ + jTile + ty * 4) = o;
    }
}

// ---------------------------------------------------------------------------
// K3: out[e][c] = (LN_d(t[e][:]) @ p_out_w^T)[c] * sigmoid(xn[e][:] @ g_out_w^T)[c]
// Block: 32 elements x 64 output channels (grid.y = 2 halves).
// Ts/Xs held [d][e] in smem; weights staged in 32-d chunks; Wb doubles as
// LN reduction scratch before weights are loaded.
// ---------------------------------------------------------------------------
__global__ void __launch_bounds__(256)
k3_out(const float* __restrict__ nw, const float* __restrict__ nb,
       const float* __restrict__ powt, const float* __restrict__ gowt,
       float* __restrict__ out) {
    __shared__ float Ts[HD][32];       // t, then normalized t  [d][e]
    __shared__ float Xs[HD][32];       // xn transposed          [d][e]
    __shared__ float Wb[2][32][64];    // staged weights / LN scratch
    int tid = threadIdx.x;
    int e0 = blockIdx.x * 32;
    int c0 = blockIdx.y * 64;

    // load t tile: coalesced per-d rows of 32
    #pragma unroll
    for (int rep = 0; rep < 16; rep++) {
        int f = tid + rep * 256;    // 0..4095
        int e = f & 31;
        int dd = f >> 5;
        Ts[dd][e] = g_t[(size_t)dd * NROWS + e0 + e];
    }
    // load xn tile transposed
    #pragma unroll
    for (int rep = 0; rep < 4; rep++) {
        int f  = tid + rep * 256;   // 0..1023
        int e  = f & 31;
        int d4 = f >> 5;            // 0..31
        float4 v = *(const float4*)(g_xn + (size_t)(e0 + e) * CHN + d4 * 4);
        Xs[d4*4+0][e] = v.x; Xs[d4*4+1][e] = v.y;
        Xs[d4*4+2][e] = v.z; Xs[d4*4+3][e] = v.w;
    }
    __syncthreads();

    // LayerNorm over d for each of the 32 elements (Wb as scratch)
    float* red  = &Wb[0][0][0];        // 256
    float* red2 = red + 256;           // 256
    float* mS   = red2 + 256;          // 32
    float* rS   = mS + 32;             // 32
    {
        int e = tid & 31;
        int dc = tid >> 5;             // 0..7, 16 d's each
        float s = 0.f, q = 0.f;
        #pragma unroll
        for (int u = 0; u < 16; u++) {
            float v = Ts[dc * 16 + u][e];
            s += v; q += v * v;
        }
        red [dc * 32 + e] = s;
        red2[dc * 32 + e] = q;
    }
    __syncthreads();
    if (tid < 32) {
        float s = 0.f, q = 0.f;
        #pragma unroll
        for (int c = 0; c < 8; c++) { s += red[c * 32 + tid]; q += red2[c * 32 + tid]; }
        float mean = s * (1.0f / HD);
        float var  = q * (1.0f / HD) - mean * mean;
        mS[tid] = mean;
        rS[tid] = rsqrtf(var + 1e-5f);
    }
    __syncthreads();
    {
        int e = tid & 31;
        int dc = tid >> 5;
        float mean = mS[e], rstd = rS[e];
        #pragma unroll
        for (int u = 0; u < 16; u++) {
            int dd = dc * 16 + u;
            Ts[dd][e] = (Ts[dd][e] - mean) * rstd * nw[dd] + nb[dd];
        }
    }

    // dual GEMM: 32e x 64c, staged over d
    int tx = tid & 7;      // e = tx*4 + i
    int ty = tid >> 3;     // c = ty*2 + j
    float accO[4][2] = {}, accGt[4][2] = {};
    for (int d0 = 0; d0 < HD; d0 += 32) {
        __syncthreads();   // previous consumers of Wb done (also covers LN scratch)
        #pragma unroll
        for (int rep = 0; rep < 2; rep++) {
            int f  = tid + rep * 256;  // 0..511
            int c  = f & 63;
            int d4 = f >> 6;           // 0..7
            float4 pv = *(const float4*)(powt + (size_t)(c0 + c) * HD + d0 + d4 * 4);
            Wb[0][d4*4+0][c] = pv.x; Wb[0][d4*4+1][c] = pv.y;
            Wb[0][d4*4+2][c] = pv.z; Wb[0][d4*4+3][c] = pv.w;
            float4 gv = *(const float4*)(gowt + (size_t)(c0 + c) * CHN + d0 + d4 * 4);
            Wb[1][d4*4+0][c] = gv.x; Wb[1][d4*4+1][c] = gv.y;
            Wb[1][d4*4+2][c] = gv.z; Wb[1][d4*4+3][c] = gv.w;
        }
        __syncthreads();
        #pragma unroll 8
        for (int dd = 0; dd < 32; dd++) {
            int d = d0 + dd;
            float4 on = *(const float4*)&Ts[d][tx * 4];
            float4 xv = *(const float4*)&Xs[d][tx * 4];
            float2 wp = *(const float2*)&Wb[0][dd][ty * 2];
            float2 wg = *(const float2*)&Wb[1][dd][ty * 2];
            float onv[4] = {on.x, on.y, on.z, on.w};
            float xvv[4] = {xv.x, xv.y, xv.z, xv.w};
            float wpv[2] = {wp.x, wp.y};
            float wgv[2] = {wg.x, wg.y};
            #pragma unroll
            for (int i = 0; i < 4; i++)
                #pragma unroll
                for (int j = 0; j < 2; j++) {
                    accO [i][j] += onv[i] * wpv[j];
                    accGt[i][j] += xvv[i] * wgv[j];
                }
        }
    }

    #pragma unroll
    for (int i = 0; i < 4; i++) {
        int e = e0 + tx * 4 + i;
        float2 o;
        o.x = accO[i][0] / (1.0f + __expf(-accGt[i][0]));
        o.y = accO[i][1] / (1.0f + __expf(-accGt[i][1]));
        *(float2*)(out + (size_t)e * CHN + c0 + ty * 2) = o;
    }
}

// ---------------------------------------------------------------------------
extern "C" void kernel_launch(void* const* d_in, const int* in_sizes, int n_in,
                              void* d_out, int out_size) {
    const float* x      = (const float*)d_in[0];
    const float* nin_w  = (const float*)d_in[1];
    const float* nin_b  = (const float*)d_in[2];
    const float* p_in_w = (const float*)d_in[3];
    const float* g_in_w = (const float*)d_in[4];
    const float* nout_w = (const float*)d_in[5];
    const float* nout_b = (const float*)d_in[6];
    const float* p_out_w = (const float*)d_in[7];
    const float* g_out_w = (const float*)d_in[8];
    float* out = (float*)d_out;

    k0_ln   <<<NROWS / 8, dim3(32, 8)>>>(x, nin_w, nin_b);
    k1_proj <<<dim3(NROWS / 64, 4), 256>>>(p_in_w, g_in_w);
    k2_einsum<<<dim3(NSEQ / 64, NSEQ / 64, HD), 256>>>();
    k3_out  <<<dim3(NROWS / 32, 2), 256>>>(nout_w, nout_b, p_out_w, g_out_w, out);
}

// round 2
// speedup vs baseline: 1.8566x; 1.8566x over previous
#include <cuda_runtime.h>
#include <math.h>

#define NSEQ 512
#define CHN  128
#define HD   128
#define NROWS (NSEQ*NSEQ)   // 262144

// Scratch (__device__ globals: allocation-free per harness rules)
__device__ float g_xn[(size_t)NROWS * CHN];   // LN(x) row-major [row][c]  (tf32-rounded)
__device__ float g_a [(size_t)HD * NROWS];    // channel-major [d][i*512+k] (tf32-rounded)
__device__ float g_b [(size_t)HD * NROWS];    // channel-major [d][j*512+k] (tf32-rounded)
__device__ float g_t [(size_t)HD * NROWS];    // channel-major [d][i*512+j] (fp32)

// ---------------------------------------------------------------------------
// helpers
// ---------------------------------------------------------------------------
__device__ __forceinline__ float tf32r(float f) {
    unsigned u;
    asm("cvt.rna.tf32.f32 %0, %1;" : "=r"(u) : "f"(f));
    return __uint_as_float(u);
}

__device__ __forceinline__ void mma_tf32(float* c, const unsigned* a, const unsigned* b) {
    asm volatile(
        "mma.sync.aligned.m16n8k8.row.col.f32.tf32.tf32.f32 "
        "{%0,%1,%2,%3}, {%4,%5,%6,%7}, {%8,%9}, {%0,%1,%2,%3};\n"
        : "+f"(c[0]), "+f"(c[1]), "+f"(c[2]), "+f"(c[3])
        : "r"(a[0]), "r"(a[1]), "r"(a[2]), "r"(a[3]), "r"(b[0]), "r"(b[1]));
}

// ---------------------------------------------------------------------------
// K0: xn = LayerNorm(x) over C=128.  One warp per row; output tf32-rounded.
// ---------------------------------------------------------------------------
__global__ void k0_ln(const float* __restrict__ x,
                      const float* __restrict__ w,
                      const float* __restrict__ b) {
    int row  = blockIdx.x * blockDim.y + threadIdx.y;
    int lane = threadIdx.x;
    const float* xr = x + (size_t)row * CHN;
    float4 v = *(const float4*)(xr + lane * 4);
    float s = v.x + v.y + v.z + v.w;
    float q = v.x*v.x + v.y*v.y + v.z*v.z + v.w*v.w;
    #pragma unroll
    for (int o = 16; o > 0; o >>= 1) {
        s += __shfl_xor_sync(0xffffffffu, s, o);
        q += __shfl_xor_sync(0xffffffffu, q, o);
    }
    float mean = s * (1.0f / CHN);
    float var  = q * (1.0f / CHN) - mean * mean;
    float rstd = rsqrtf(var + 1e-5f);
    float4 wv = *(const float4*)(w + lane * 4);
    float4 bv = *(const float4*)(b + lane * 4);
    float4 o;
    o.x = tf32r((v.x - mean) * rstd * wv.x + bv.x);
    o.y = tf32r((v.y - mean) * rstd * wv.y + bv.y);
    o.z = tf32r((v.z - mean) * rstd * wv.z + bv.z);
    o.w = tf32r((v.w - mean) * rstd * wv.w + bv.w);
    *(float4*)(g_xn + (size_t)row * CHN + lane * 4) = o;
}

// ---------------------------------------------------------------------------
// K1 (tf32 MMA): h = (xn @ p_in_w^T) * sigmoid(xn @ g_in_w^T)
// CTA: 128 rows x 64 channels (dual P/G accumulators), K=128 staged by 32.
// 8 warps = 4(i) x 2(ch); warp tile 32x32, 2xm16 x 4xn8, dual.
// Output written channel-major (g_a ch<128 / g_b ch>=128), tf32-rounded.
// ---------------------------------------------------------------------------
__global__ void __launch_bounds__(256)
k1_proj(const float* __restrict__ pw, const float* __restrict__ gw) {
    __shared__ float sm[(128 + 64 + 64) * 36];
    float* As = sm;             // [128][36]  xn tile (k-stage 32 + pad)
    float* Ps = sm + 128 * 36;  // [64][36]
    float* Gs = sm + 192 * 36;  // [64][36]

    int tid = threadIdx.x;
    int rowTile = blockIdx.x * 128;
    int chTile  = blockIdx.y * 64;       // 0..192 over 2H=256
    int w = tid >> 5, lane = tid & 31;
    int wi = w & 3, wj = w >> 2;
    int gid = lane >> 2, tig = lane & 3;

    float accP[2][4][4] = {}, accG[2][4][4] = {};

    for (int k0 = 0; k0 < CHN; k0 += 32) {
        #pragma unroll
        for (int rep = 0; rep < 4; rep++) {
            int f = tid + rep * 256;          // 0..1023
            int k4 = f & 7, r = f >> 3;       // r 0..127
            float4 v = *(const float4*)(g_xn + (size_t)(rowTile + r) * CHN + k0 + k4 * 4);
            *(float4*)(As + r * 36 + k4 * 4) = v;   // already tf32 bits
        }
        #pragma unroll
        for (int rep = 0; rep < 2; rep++) {
            int f = tid + rep * 256;          // 0..511
            int k4 = f & 7, c = f >> 3;       // c 0..63
            float4 v = *(const float4*)(pw + (size_t)(chTile + c) * CHN + k0 + k4 * 4);
            v.x = tf32r(v.x); v.y = tf32r(v.y); v.z = tf32r(v.z); v.w = tf32r(v.w);
            *(float4*)(Ps + c * 36 + k4 * 4) = v;
            float4 u = *(const float4*)(gw + (size_t)(chTile + c) * CHN + k0 + k4 * 4);
            u.x = tf32r(u.x); u.y = tf32r(u.y); u.z = tf32r(u.z); u.w = tf32r(u.w);
            *(float4*)(Gs + c * 36 + k4 * 4) = u;
        }
        __syncthreads();

        #pragma unroll
        for (int kk = 0; kk < 4; kk++) {
            int kb = kk * 8;
            unsigned a[2][4];
            #pragma unroll
            for (int mi = 0; mi < 2; mi++) {
                int r0 = wi * 32 + mi * 16 + gid;
                a[mi][0] = __float_as_uint(As[r0 * 36 + kb + tig]);
                a[mi][1] = __float_as_uint(As[(r0 + 8) * 36 + kb + tig]);
                a[mi][2] = __float_as_uint(As[r0 * 36 + kb + tig + 4]);
                a[mi][3] = __float_as_uint(As[(r0 + 8) * 36 + kb + tig + 4]);
            }
            #pragma unroll
            for (int nj = 0; nj < 4; nj++) {
                int n0 = wj * 32 + nj * 8 + gid;
                unsigned pb[2], gb[2];
                pb[0] = __float_as_uint(Ps[n0 * 36 + kb + tig]);
                pb[1] = __float_as_uint(Ps[n0 * 36 + kb + tig + 4]);
                gb[0] = __float_as_uint(Gs[n0 * 36 + kb + tig]);
                gb[1] = __float_as_uint(Gs[n0 * 36 + kb + tig + 4]);
                #pragma unroll
                for (int mi = 0; mi < 2; mi++) {
                    mma_tf32(accP[mi][nj], a[mi], pb);
                    mma_tf32(accG[mi][nj], a[mi], gb);
                }
            }
        }
        __syncthreads();
    }

    // epilogue: h = P * sigmoid(G); per-warp smem transpose -> channel-major
    float* Hs = sm + w * (32 * 33);   // [32 ch][33]
    #pragma unroll
    for (int mi = 0; mi < 2; mi++)
        #pragma unroll
        for (int nj = 0; nj < 4; nj++)
            #pragma unroll
            for (int c = 0; c < 4; c++) {
                float h = accP[mi][nj][c] / (1.0f + __expf(-accG[mi][nj][c]));
                int row = mi * 16 + gid + ((c >> 1) << 3);
                int ch  = nj * 8 + tig * 2 + (c & 1);
                Hs[ch * 33 + row] = tf32r(h);
            }
    __syncwarp();
    {
        int chG = chTile + wj * 32 + lane;
        float* dst = (chG < HD) ? (g_a + (size_t)chG * NROWS)
                                : (g_b + (size_t)(chG - HD) * NROWS);
        size_t base = (size_t)rowTile + wi * 32;
        #pragma unroll
        for (int r4 = 0; r4 < 8; r4++) {
            float4 o;
            o.x = Hs[lane * 33 + r4 * 4 + 0];
            o.y = Hs[lane * 33 + r4 * 4 + 1];
            o.z = Hs[lane * 33 + r4 * 4 + 2];
            o.w = Hs[lane * 33 + r4 * 4 + 3];
            *(float4*)(dst + base + r4 * 4) = o;
        }
    }
}

// ---------------------------------------------------------------------------
// K2 (tf32 MMA): t[d][i][j] = sum_k a[d][i][k] * b[d][j][k]
// 128 independent 512x512x512 NT GEMMs. CTA tile 128x128, K staged by 32.
// 8 warps = 4(i) x 2(j); warp tile 32x64 = 2xm16 x 8xn8.
// ---------------------------------------------------------------------------
__global__ void __launch_bounds__(256)
k2_einsum() {
    __shared__ float As[128 * 36];   // [i][k] pad 4
    __shared__ float Bs[128 * 36];   // [j][k] pad 4
    int tid = threadIdx.x;
    int d = blockIdx.z;
    int iTile = blockIdx.x * 128;
    int jTile = blockIdx.y * 128;
    const float* Ab = g_a + (size_t)d * NROWS;
    const float* Bb = g_b + (size_t)d * NROWS;
    int w = tid >> 5, lane = tid & 31;
    int wi = w & 3, wj = w >> 2;
    int gid = lane >> 2, tig = lane & 3;

    float acc[2][8][4] = {};

    for (int k0 = 0; k0 < NSEQ; k0 += 32) {
        #pragma unroll
        for (int rep = 0; rep < 4; rep++) {
            int f = tid + rep * 256;
            int k4 = f & 7, r = f >> 3;
            float4 av = *(const float4*)(Ab + (size_t)(iTile + r) * NSEQ + k0 + k4 * 4);
            *(float4*)(As + r * 36 + k4 * 4) = av;
            float4 bv = *(const float4*)(Bb + (size_t)(jTile + r) * NSEQ + k0 + k4 * 4);
            *(float4*)(Bs + r * 36 + k4 * 4) = bv;
        }
        __syncthreads();

        #pragma unroll
        for (int kk = 0; kk < 4; kk++) {
            int kb = kk * 8;
            unsigned a[2][4];
            #pragma unroll
            for (int mi = 0; mi < 2; mi++) {
                int r0 = wi * 32 + mi * 16 + gid;
                a[mi][0] = __float_as_uint(As[r0 * 36 + kb + tig]);
                a[mi][1] = __float_as_uint(As[(r0 + 8) * 36 + kb + tig]);
                a[mi][2] = __float_as_uint(As[r0 * 36 + kb + tig + 4]);
                a[mi][3] = __float_as_uint(As[(r0 + 8) * 36 + kb + tig + 4]);
            }
            #pragma unroll
            for (int nj = 0; nj < 8; nj++) {
                int n0 = wj * 64 + nj * 8 + gid;
                unsigned b[2];
                b[0] = __float_as_uint(Bs[n0 * 36 + kb + tig]);
                b[1] = __float_as_uint(Bs[n0 * 36 + kb + tig + 4]);
                #pragma unroll
                for (int mi = 0; mi < 2; mi++)
                    mma_tf32(acc[mi][nj], a[mi], b);
            }
        }
        __syncthreads();
    }

    float* T = g_t + (size_t)d * NROWS;
    #pragma unroll
    for (int mi = 0; mi < 2; mi++)
        #pragma unroll
        for (int nj = 0; nj < 8; nj++) {
            int r0 = iTile + wi * 32 + mi * 16 + gid;
            int cj = jTile + wj * 64 + nj * 8 + tig * 2;
            float2 v0 = make_float2(acc[mi][nj][0], acc[mi][nj][1]);
            *(float2*)(T + (size_t)r0 * NSEQ + cj) = v0;
            float2 v1 = make_float2(acc[mi][nj][2], acc[mi][nj][3]);
            *(float2*)(T + (size_t)(r0 + 8) * NSEQ + cj) = v1;
        }
}

// ---------------------------------------------------------------------------
// K3 (unchanged SIMT): out = (LN_d(t) @ p_out^T) * sigmoid(xn @ g_out^T)
// ---------------------------------------------------------------------------
__global__ void __launch_bounds__(256)
k3_out(const float* __restrict__ nw, const float* __restrict__ nb,
       const float* __restrict__ powt, const float* __restrict__ gowt,
       float* __restrict__ out) {
    __shared__ float Ts[HD][32];
    __shared__ float Xs[HD][32];
    __shared__ float Wb[2][32][64];
    int tid = threadIdx.x;
    int e0 = blockIdx.x * 32;
    int c0 = blockIdx.y * 64;

    #pragma unroll
    for (int rep = 0; rep < 16; rep++) {
        int f = tid + rep * 256;
        int e = f & 31;
        int dd = f >> 5;
        Ts[dd][e] = g_t[(size_t)dd * NROWS + e0 + e];
    }
    #pragma unroll
    for (int rep = 0; rep < 4; rep++) {
        int f  = tid + rep * 256;
        int e  = f & 31;
        int d4 = f >> 5;
        float4 v = *(const float4*)(g_xn + (size_t)(e0 + e) * CHN + d4 * 4);
        Xs[d4*4+0][e] = v.x; Xs[d4*4+1][e] = v.y;
        Xs[d4*4+2][e] = v.z; Xs[d4*4+3][e] = v.w;
    }
    __syncthreads();

    float* red  = &Wb[0][0][0];
    float* red2 = red + 256;
    float* mS   = red2 + 256;
    float* rS   = mS + 32;
    {
        int e = tid & 31;
        int dc = tid >> 5;
        float s = 0.f, q = 0.f;
        #pragma unroll
        for (int u = 0; u < 16; u++) {
            float v = Ts[dc * 16 + u][e];
            s += v; q += v * v;
        }
        red [dc * 32 + e] = s;
        red2[dc * 32 + e] = q;
    }
    __syncthreads();
    if (tid < 32) {
        float s = 0.f, q = 0.f;
        #pragma unroll
        for (int c = 0; c < 8; c++) { s += red[c * 32 + tid]; q += red2[c * 32 + tid]; }
        float mean = s * (1.0f / HD);
        float var  = q * (1.0f / HD) - mean * mean;
        mS[tid] = mean;
        rS[tid] = rsqrtf(var + 1e-5f);
    }
    __syncthreads();
    {
        int e = tid & 31;
        int dc = tid >> 5;
        float mean = mS[e], rstd = rS[e];
        #pragma unroll
        for (int u = 0; u < 16; u++) {
            int dd = dc * 16 + u;
            Ts[dd][e] = (Ts[dd][e] - mean) * rstd * nw[dd] + nb[dd];
        }
    }

    int tx = tid & 7;
    int ty = tid >> 3;
    float accO[4][2] = {}, accGt[4][2] = {};
    for (int d0 = 0; d0 < HD; d0 += 32) {
        __syncthreads();
        #pragma unroll
        for (int rep = 0; rep < 2; rep++) {
            int f  = tid + rep * 256;
            int c  = f & 63;
            int d4 = f >> 6;
            float4 pv = *(const float4*)(powt + (size_t)(c0 + c) * HD + d0 + d4 * 4);
            Wb[0][d4*4+0][c] = pv.x; Wb[0][d4*4+1][c] = pv.y;
            Wb[0][d4*4+2][c] = pv.z; Wb[0][d4*4+3][c] = pv.w;
            float4 gv = *(const float4*)(gowt + (size_t)(c0 + c) * CHN + d0 + d4 * 4);
            Wb[1][d4*4+0][c] = gv.x; Wb[1][d4*4+1][c] = gv.y;
            Wb[1][d4*4+2][c] = gv.z; Wb[1][d4*4+3][c] = gv.w;
        }
        __syncthreads();
        #pragma unroll 8
        for (int dd = 0; dd < 32; dd++) {
            int d = d0 + dd;
            float4 on = *(const float4*)&Ts[d][tx * 4];
            float4 xv = *(const float4*)&Xs[d][tx * 4];
            float2 wp = *(const float2*)&Wb[0][dd][ty * 2];
            float2 wg = *(const float2*)&Wb[1][dd][ty * 2];
            float onv[4] = {on.x, on.y, on.z, on.w};
            float xvv[4] = {xv.x, xv.y, xv.z, xv.w};
            float wpv[2] = {wp.x, wp.y};
            float wgv[2] = {wg.x, wg.y};
            #pragma unroll
            for (int i = 0; i < 4; i++)
                #pragma unroll
                for (int j = 0; j < 2; j++) {
                    accO [i][j] += onv[i] * wpv[j];
                    accGt[i][j] += xvv[i] * wgv[j];
                }
        }
    }

    #pragma unroll
    for (int i = 0; i < 4; i++) {
        int e = e0 + tx * 4 + i;
        float2 o;
        o.x = accO[i][0] / (1.0f + __expf(-accGt[i][0]));
        o.y = accO[i][1] / (1.0f + __expf(-accGt[i][1]));
        *(float2*)(out + (size_t)e * CHN + c0 + ty * 2) = o;
    }
}

// ---------------------------------------------------------------------------
extern "C" void kernel_launch(void* const* d_in, const int* in_sizes, int n_in,
                              void* d_out, int out_size) {
    const float* x       = (const float*)d_in[0];
    const float* nin_w   = (const float*)d_in[1];
    const float* nin_b   = (const float*)d_in[2];
    const float* p_in_w  = (const float*)d_in[3];
    const float* g_in_w  = (const float*)d_in[4];
    const float* nout_w  = (const float*)d_in[5];
    const float* nout_b  = (const float*)d_in[6];
    const float* p_out_w = (const float*)d_in[7];
    const float* g_out_w = (const float*)d_in[8];
    float* out = (float*)d_out;

    k0_ln    <<<NROWS / 8, dim3(32, 8)>>>(x, nin_w, nin_b);
    k1_proj  <<<dim3(NROWS / 128, 4), 256>>>(p_in_w, g_in_w);
    k2_einsum<<<dim3(NSEQ / 128, NSEQ / 128, HD), 256>>>();
    k3_out   <<<dim3(NROWS / 32, 2), 256>>>(nout_w, nout_b, p_out_w, g_out_w, out);
}

// round 5
// speedup vs baseline: 3.0957x; 1.6674x over previous
#include <cuda_runtime.h>
#include <math.h>

#define NSEQ 512
#define CHN  128
#define HD   128
#define NROWS (NSEQ*NSEQ)   // 262144

// Scratch (__device__ globals: allocation-free per harness rules)
__device__ float g_xn[(size_t)NROWS * CHN];   // LN(x) row-major [row][c]  (tf32-rounded)
__device__ float g_a [(size_t)HD * NROWS];    // channel-major [d][i*512+k] (tf32-rounded)
__device__ float g_b [(size_t)HD * NROWS];    // channel-major [d][j*512+k] (tf32-rounded)
__device__ float g_t [(size_t)HD * NROWS];    // channel-major [d][i*512+j] (fp32)
__device__ float g_tn[(size_t)NROWS * HD];    // LN_d(t) row-major [e][d]   (tf32-rounded)

// ---------------------------------------------------------------------------
// helpers
// ---------------------------------------------------------------------------
__device__ __forceinline__ float tf32r(float f) {
    unsigned u;
    asm("cvt.rna.tf32.f32 %0, %1;" : "=r"(u) : "f"(f));
    return __uint_as_float(u);
}

__device__ __forceinline__ void mma_tf32(float* c, const unsigned* a, const unsigned* b) {
    asm volatile(
        "mma.sync.aligned.m16n8k8.row.col.f32.tf32.tf32.f32 "
        "{%0,%1,%2,%3}, {%4,%5,%6,%7}, {%8,%9}, {%0,%1,%2,%3};\n"
        : "+f"(c[0]), "+f"(c[1]), "+f"(c[2]), "+f"(c[3])
        : "r"(a[0]), "r"(a[1]), "r"(a[2]), "r"(a[3]), "r"(b[0]), "r"(b[1]));
}

// ---------------------------------------------------------------------------
// K0: xn = LayerNorm(x) over C=128.  One warp per row; output tf32-rounded.
// ---------------------------------------------------------------------------
__global__ void k0_ln(const float* __restrict__ x,
                      const float* __restrict__ w,
                      const float* __restrict__ b) {
    int row  = blockIdx.x * blockDim.y + threadIdx.y;
    int lane = threadIdx.x;
    const float* xr = x + (size_t)row * CHN;
    float4 v = *(const float4*)(xr + lane * 4);
    float s = v.x + v.y + v.z + v.w;
    float q = v.x*v.x + v.y*v.y + v.z*v.z + v.w*v.w;
    #pragma unroll
    for (int o = 16; o > 0; o >>= 1) {
        s += __shfl_xor_sync(0xffffffffu, s, o);
        q += __shfl_xor_sync(0xffffffffu, q, o);
    }
    float mean = s * (1.0f / CHN);
    float var  = q * (1.0f / CHN) - mean * mean;
    float rstd = rsqrtf(var + 1e-5f);
    float4 wv = *(const float4*)(w + lane * 4);
    float4 bv = *(const float4*)(b + lane * 4);
    float4 o;
    o.x = tf32r((v.x - mean) * rstd * wv.x + bv.x);
    o.y = tf32r((v.y - mean) * rstd * wv.y + bv.y);
    o.z = tf32r((v.z - mean) * rstd * wv.z + bv.z);
    o.w = tf32r((v.w - mean) * rstd * wv.w + bv.w);
    *(float4*)(g_xn + (size_t)row * CHN + lane * 4) = o;
}

// ---------------------------------------------------------------------------
// K1 (tf32 MMA): h = (xn @ p_in_w^T) * sigmoid(xn @ g_in_w^T)
// CTA: 128 rows x 64 channels (dual P/G accumulators), K=128 staged by 32.
// Output written channel-major (g_a ch<128 / g_b ch>=128), tf32-rounded.
// ---------------------------------------------------------------------------
__global__ void __launch_bounds__(256)
k1_proj(const float* __restrict__ pw, const float* __restrict__ gw) {
    __shared__ float sm[(128 + 64 + 64) * 36];
    float* As = sm;             // [128][36]
    float* Ps = sm + 128 * 36;  // [64][36]
    float* Gs = sm + 192 * 36;  // [64][36]

    int tid = threadIdx.x;
    int rowTile = blockIdx.x * 128;
    int chTile  = blockIdx.y * 64;
    int w = tid >> 5, lane = tid & 31;
    int wi = w & 3, wj = w >> 2;
    int gid = lane >> 2, tig = lane & 3;

    float accP[2][4][4] = {}, accG[2][4][4] = {};

    for (int k0 = 0; k0 < CHN; k0 += 32) {
        #pragma unroll
        for (int rep = 0; rep < 4; rep++) {
            int f = tid + rep * 256;
            int k4 = f & 7, r = f >> 3;
            float4 v = *(const float4*)(g_xn + (size_t)(rowTile + r) * CHN + k0 + k4 * 4);
            *(float4*)(As + r * 36 + k4 * 4) = v;
        }
        #pragma unroll
        for (int rep = 0; rep < 2; rep++) {
            int f = tid + rep * 256;
            int k4 = f & 7, c = f >> 3;
            float4 v = *(const float4*)(pw + (size_t)(chTile + c) * CHN + k0 + k4 * 4);
            v.x = tf32r(v.x); v.y = tf32r(v.y); v.z = tf32r(v.z); v.w = tf32r(v.w);
            *(float4*)(Ps + c * 36 + k4 * 4) = v;
            float4 u = *(const float4*)(gw + (size_t)(chTile + c) * CHN + k0 + k4 * 4);
            u.x = tf32r(u.x); u.y = tf32r(u.y); u.z = tf32r(u.z); u.w = tf32r(u.w);
            *(float4*)(Gs + c * 36 + k4 * 4) = u;
        }
        __syncthreads();

        #pragma unroll
        for (int kk = 0; kk < 4; kk++) {
            int kb = kk * 8;
            unsigned a[2][4];
            #pragma unroll
            for (int mi = 0; mi < 2; mi++) {
                int r0 = wi * 32 + mi * 16 + gid;
                a[mi][0] = __float_as_uint(As[r0 * 36 + kb + tig]);
                a[mi][1] = __float_as_uint(As[(r0 + 8) * 36 + kb + tig]);
                a[mi][2] = __float_as_uint(As[r0 * 36 + kb + tig + 4]);
                a[mi][3] = __float_as_uint(As[(r0 + 8) * 36 + kb + tig + 4]);
            }
            #pragma unroll
            for (int nj = 0; nj < 4; nj++) {
                int n0 = wj * 32 + nj * 8 + gid;
                unsigned pb[2], gb[2];
                pb[0] = __float_as_uint(Ps[n0 * 36 + kb + tig]);
                pb[1] = __float_as_uint(Ps[n0 * 36 + kb + tig + 4]);
                gb[0] = __float_as_uint(Gs[n0 * 36 + kb + tig]);
                gb[1] = __float_as_uint(Gs[n0 * 36 + kb + tig + 4]);
                #pragma unroll
                for (int mi = 0; mi < 2; mi++) {
                    mma_tf32(accP[mi][nj], a[mi], pb);
                    mma_tf32(accG[mi][nj], a[mi], gb);
                }
            }
        }
        __syncthreads();
    }

    // epilogue: h = P * sigmoid(G); per-warp smem transpose -> channel-major
    float* Hs = sm + w * (32 * 33);
    #pragma unroll
    for (int mi = 0; mi < 2; mi++)
        #pragma unroll
        for (int nj = 0; nj < 4; nj++)
            #pragma unroll
            for (int c = 0; c < 4; c++) {
                float h = accP[mi][nj][c] / (1.0f + __expf(-accG[mi][nj][c]));
                int row = mi * 16 + gid + ((c >> 1) << 3);
                int ch  = nj * 8 + tig * 2 + (c & 1);
                Hs[ch * 33 + row] = tf32r(h);
            }
    __syncwarp();
    {
        int chG = chTile + wj * 32 + lane;
        float* dst = (chG < HD) ? (g_a + (size_t)chG * NROWS)
                                : (g_b + (size_t)(chG - HD) * NROWS);
        size_t base = (size_t)rowTile + wi * 32;
        #pragma unroll
        for (int r4 = 0; r4 < 8; r4++) {
            float4 o;
            o.x = Hs[lane * 33 + r4 * 4 + 0];
            o.y = Hs[lane * 33 + r4 * 4 + 1];
            o.z = Hs[lane * 33 + r4 * 4 + 2];
            o.w = Hs[lane * 33 + r4 * 4 + 3];
            *(float4*)(dst + base + r4 * 4) = o;
        }
    }
}

// ---------------------------------------------------------------------------
// K2 (tf32 MMA): t[d][i][j] = sum_k a[d][i][k] * b[d][j][k]
// 128 independent 512x512x512 NT GEMMs. CTA tile 128x128, K staged by 32.
// ---------------------------------------------------------------------------
__global__ void __launch_bounds__(256)
k2_einsum() {
    __shared__ float As[128 * 36];
    __shared__ float Bs[128 * 36];
    int tid = threadIdx.x;
    int d = blockIdx.z;
    int iTile = blockIdx.x * 128;
    int jTile = blockIdx.y * 128;
    const float* Ab = g_a + (size_t)d * NROWS;
    const float* Bb = g_b + (size_t)d * NROWS;
    int w = tid >> 5, lane = tid & 31;
    int wi = w & 3, wj = w >> 2;
    int gid = lane >> 2, tig = lane & 3;

    float acc[2][8][4] = {};

    for (int k0 = 0; k0 < NSEQ; k0 += 32) {
        #pragma unroll
        for (int rep = 0; rep < 4; rep++) {
            int f = tid + rep * 256;
            int k4 = f & 7, r = f >> 3;
            float4 av = *(const float4*)(Ab + (size_t)(iTile + r) * NSEQ + k0 + k4 * 4);
            *(float4*)(As + r * 36 + k4 * 4) = av;
            float4 bv = *(const float4*)(Bb + (size_t)(jTile + r) * NSEQ + k0 + k4 * 4);
            *(float4*)(Bs + r * 36 + k4 * 4) = bv;
        }
        __syncthreads();

        #pragma unroll
        for (int kk = 0; kk < 4; kk++) {
            int kb = kk * 8;
            unsigned a[2][4];
            #pragma unroll
            for (int mi = 0; mi < 2; mi++) {
                int r0 = wi * 32 + mi * 16 + gid;
                a[mi][0] = __float_as_uint(As[r0 * 36 + kb + tig]);
                a[mi][1] = __float_as_uint(As[(r0 + 8) * 36 + kb + tig]);
                a[mi][2] = __float_as_uint(As[r0 * 36 + kb + tig + 4]);
                a[mi][3] = __float_as_uint(As[(r0 + 8) * 36 + kb + tig + 4]);
            }
            #pragma unroll
            for (int nj = 0; nj < 8; nj++) {
                int n0 = wj * 64 + nj * 8 + gid;
                unsigned b[2];
                b[0] = __float_as_uint(Bs[n0 * 36 + kb + tig]);
                b[1] = __float_as_uint(Bs[n0 * 36 + kb + tig + 4]);
                #pragma unroll
                for (int mi = 0; mi < 2; mi++)
                    mma_tf32(acc[mi][nj], a[mi], b);
            }
        }
        __syncthreads();
    }

    float* T = g_t + (size_t)d * NROWS;
    #pragma unroll
    for (int mi = 0; mi < 2; mi++)
        #pragma unroll
        for (int nj = 0; nj < 8; nj++) {
            int r0 = iTile + wi * 32 + mi * 16 + gid;
            int cj = jTile + wj * 64 + nj * 8 + tig * 2;
            float2 v0 = make_float2(acc[mi][nj][0], acc[mi][nj][1]);
            *(float2*)(T + (size_t)r0 * NSEQ + cj) = v0;
            float2 v1 = make_float2(acc[mi][nj][2], acc[mi][nj][3]);
            *(float2*)(T + (size_t)(r0 + 8) * NSEQ + cj) = v1;
        }
}

// ---------------------------------------------------------------------------
// K3a: tn = LayerNorm_d(t), transposing channel-major g_t -> row-major g_tn.
// Block: 64 elements, full d=128 in smem [e][d] with 132 pad.
// ---------------------------------------------------------------------------
__global__ void __launch_bounds__(256)
k3a_ln(const float* __restrict__ nw, const float* __restrict__ nb) {
    __shared__ float Ts[64][132];          // [e][d], pad 4 -> aligned float4 rows
    __shared__ float red[4][64], red2[4][64];
    __shared__ float mS[64], rS[64];
    int tid = threadIdx.x;
    int e0 = blockIdx.x * 64;

    // load transposed: global reads coalesced over e (32 consecutive per d)
    #pragma unroll
    for (int rep = 0; rep < 32; rep++) {
        int f = tid + rep * 256;           // 0..8191
        int e = f & 63;
        int d = f >> 6;                    // 0..127
        Ts[e][d] = g_t[(size_t)d * NROWS + e0 + e];
    }
    __syncthreads();

    // stats: thread (e = tid&63, dc = tid>>6) reduces 32 d's via float4
    {
        int e = tid & 63;
        int dc = tid >> 6;                 // 0..3
        float s = 0.f, q = 0.f;
        #pragma unroll
        for (int u4 = 0; u4 < 8; u4++) {
            float4 v = *(const float4*)&Ts[e][dc * 32 + u4 * 4];
            s += v.x + v.y + v.z + v.w;
            q += v.x*v.x + v.y*v.y + v.z*v.z + v.w*v.w;
        }
        red[dc][e] = s;
        red2[dc][e] = q;
    }
    __syncthreads();
    if (tid < 64) {
        float s = red[0][tid] + red[1][tid] + red[2][tid] + red[3][tid];
        float q = red2[0][tid] + red2[1][tid] + red2[2][tid] + red2[3][tid];
        float mean = s * (1.0f / HD);
        float var  = q * (1.0f / HD) - mean * mean;
        mS[tid] = mean;
        rS[tid] = rsqrtf(var + 1e-5f);
    }
    __syncthreads();

    // normalize + write row-major, coalesced over d
    {
        int d4 = tid & 31;                 // float4 index
        float4 wv = *(const float4*)(nw + d4 * 4);
        float4 bv = *(const float4*)(nb + d4 * 4);
        #pragma unroll
        for (int rep = 0; rep < 8; rep++) {
            int e = (tid >> 5) + rep * 8;
            float mean = mS[e], rstd = rS[e];
            float4 v = *(const float4*)&Ts[e][d4 * 4];
            float4 o;
            o.x = tf32r((v.x - mean) * rstd * wv.x + bv.x);
            o.y = tf32r((v.y - mean) * rstd * wv.y + bv.y);
            o.z = tf32r((v.z - mean) * rstd * wv.z + bv.z);
            o.w = tf32r((v.w - mean) * rstd * wv.w + bv.w);
            *(float4*)(g_tn + (size_t)(e0 + e) * HD + d4 * 4) = o;
        }
    }
}

// ---------------------------------------------------------------------------
// K3b (tf32 MMA): out[e][c] = (tn[e][:] @ p_out^T)[c] * sigmoid(xn[e][:] @ g_out^T)[c]
// CTA: 128 elements x 64 channels, dual GEMM with DIFFERENT A tiles
// (tn for projection, xn for gate). K staged by 16 (stride-20 smem rows,
// conflict-free; total smem 30 KB < 48 KB static limit).
// ---------------------------------------------------------------------------
#define K3_STRIDE 20
__global__ void __launch_bounds__(256)
k3b_out(const float* __restrict__ powt, const float* __restrict__ gowt,
        float* __restrict__ out) {
    __shared__ float sm[(128 + 128 + 64 + 64) * K3_STRIDE];
    float* As = sm;                      // [128][20]  tn
    float* Xs = sm + 128 * K3_STRIDE;    // [128][20]  xn
    float* Ps = sm + 256 * K3_STRIDE;    // [64][20]   p_out rows (c)
    float* Gs = sm + 320 * K3_STRIDE;    // [64][20]   g_out rows (c)

    int tid = threadIdx.x;
    int rowTile = blockIdx.x * 128;
    int chTile  = blockIdx.y * 64;
    int w = tid >> 5, lane = tid & 31;
    int wi = w & 3, wj = w >> 2;
    int gid = lane >> 2, tig = lane & 3;

    float accO[2][4][4] = {}, accG[2][4][4] = {};

    for (int k0 = 0; k0 < HD; k0 += 16) {
        #pragma unroll
        for (int rep = 0; rep < 2; rep++) {
            int f = tid + rep * 256;          // 0..511
            int k4 = f & 3, r = f >> 2;       // r 0..127, k4 0..3
            float4 v = *(const float4*)(g_tn + (size_t)(rowTile + r) * HD + k0 + k4 * 4);
            *(float4*)(As + r * K3_STRIDE + k4 * 4) = v;
            float4 u = *(const float4*)(g_xn + (size_t)(rowTile + r) * CHN + k0 + k4 * 4);
            *(float4*)(Xs + r * K3_STRIDE + k4 * 4) = u;
        }
        {
            int f = tid;                      // 0..255
            int k4 = f & 3, c = f >> 2;       // c 0..63
            float4 v = *(const float4*)(powt + (size_t)(chTile + c) * HD + k0 + k4 * 4);
            v.x = tf32r(v.x); v.y = tf32r(v.y); v.z = tf32r(v.z); v.w = tf32r(v.w);
            *(float4*)(Ps + c * K3_STRIDE + k4 * 4) = v;
            float4 u = *(const float4*)(gowt + (size_t)(chTile + c) * CHN + k0 + k4 * 4);
            u.x = tf32r(u.x); u.y = tf32r(u.y); u.z = tf32r(u.z); u.w = tf32r(u.w);
            *(float4*)(Gs + c * K3_STRIDE + k4 * 4) = u;
        }
        __syncthreads();

        #pragma unroll
        for (int kk = 0; kk < 2; kk++) {
            int kb = kk * 8;
            unsigned a[2][4], x[2][4];
            #pragma unroll
            for (int mi = 0; mi < 2; mi++) {
                int r0 = wi * 32 + mi * 16 + gid;
                a[mi][0] = __float_as_uint(As[r0 * K3_STRIDE + kb + tig]);
                a[mi][1] = __float_as_uint(As[(r0 + 8) * K3_STRIDE + kb + tig]);
                a[mi][2] = __float_as_uint(As[r0 * K3_STRIDE + kb + tig + 4]);
                a[mi][3] = __float_as_uint(As[(r0 + 8) * K3_STRIDE + kb + tig + 4]);
                x[mi][0] = __float_as_uint(Xs[r0 * K3_STRIDE + kb + tig]);
                x[mi][1] = __float_as_uint(Xs[(r0 + 8) * K3_STRIDE + kb + tig]);
                x[mi][2] = __float_as_uint(Xs[r0 * K3_STRIDE + kb + tig + 4]);
                x[mi][3] = __float_as_uint(Xs[(r0 + 8) * K3_STRIDE + kb + tig + 4]);
            }
            #pragma unroll
            for (int nj = 0; nj < 4; nj++) {
                int n0 = wj * 32 + nj * 8 + gid;
                unsigned pb[2], gb[2];
                pb[0] = __float_as_uint(Ps[n0 * K3_STRIDE + kb + tig]);
                pb[1] = __float_as_uint(Ps[n0 * K3_STRIDE + kb + tig + 4]);
                gb[0] = __float_as_uint(Gs[n0 * K3_STRIDE + kb + tig]);
                gb[1] = __float_as_uint(Gs[n0 * K3_STRIDE + kb + tig + 4]);
                #pragma unroll
                for (int mi = 0; mi < 2; mi++) {
                    mma_tf32(accO[mi][nj], a[mi], pb);
                    mma_tf32(accG[mi][nj], x[mi], gb);
                }
            }
        }
        __syncthreads();
    }

    // epilogue: out = O * sigmoid(G), direct row-major float2 stores
    #pragma unroll
    for (int mi = 0; mi < 2; mi++)
        #pragma unroll
        for (int nj = 0; nj < 4; nj++) {
            int r0 = rowTile + wi * 32 + mi * 16 + gid;
            int cj = chTile + wj * 32 + nj * 8 + tig * 2;
            float2 v0;
            v0.x = accO[mi][nj][0] / (1.0f + __expf(-accG[mi][nj][0]));
            v0.y = accO[mi][nj][1] / (1.0f + __expf(-accG[mi][nj][1]));
            *(float2*)(out + (size_t)r0 * CHN + cj) = v0;
            float2 v1;
            v1.x = accO[mi][nj][2] / (1.0f + __expf(-accG[mi][nj][2]));
            v1.y = accO[mi][nj][3] / (1.0f + __expf(-accG[mi][nj][3]));
            *(float2*)(out + (size_t)(r0 + 8) * CHN + cj) = v1;
        }
}

// ---------------------------------------------------------------------------
extern "C" void kernel_launch(void* const* d_in, const int* in_sizes, int n_in,
                              void* d_out, int out_size) {
    const float* x       = (const float*)d_in[0];
    const float* nin_w   = (const float*)d_in[1];
    const float* nin_b   = (const float*)d_in[2];
    const float* p_in_w  = (const float*)d_in[3];
    const float* g_in_w  = (const float*)d_in[4];
    const float* nout_w  = (const float*)d_in[5];
    const float* nout_b  = (const float*)d_in[6];
    const float* p_out_w = (const float*)d_in[7];
    const float* g_out_w = (const float*)d_in[8];
    float* out = (float*)d_out;

    k0_ln    <<<NROWS / 8, dim3(32, 8)>>>(x, nin_w, nin_b);
    k1_proj  <<<dim3(NROWS / 128, 4), 256>>>(p_in_w, g_in_w);
    k2_einsum<<<dim3(NSEQ / 128, NSEQ / 128, HD), 256>>>();
    k3a_ln   <<<NROWS / 64, 256>>>(nout_w, nout_b);
    k3b_out  <<<dim3(NROWS / 128, 2), 256>>>(p_out_w, g_out_w, out);
}

// round 8
// speedup vs baseline: 3.5793x; 1.1562x over previous
#include <cuda_runtime.h>
#include <math.h>
#include <stdint.h>

#define NSEQ 512
#define CHN  128
#define HD   128
#define NROWS (NSEQ*NSEQ)   // 262144

// Scratch (__device__ globals: allocation-free per harness rules)
__device__ float g_xn[(size_t)NROWS * CHN];   // LN(x) row-major [row][c]  (tf32-rounded)
__device__ float g_a [(size_t)HD * NROWS];    // channel-major [d][i*512+k] (tf32-rounded)
__device__ float g_b [(size_t)HD * NROWS];    // channel-major [d][j*512+k] (tf32-rounded)
__device__ float g_t [(size_t)HD * NROWS];    // channel-major [d][i*512+j] (fp32)
__device__ float g_tn[(size_t)NROWS * HD];    // LN_d(t) row-major [e][d]   (tf32-rounded)

// ---------------------------------------------------------------------------
// helpers
// ---------------------------------------------------------------------------
__device__ __forceinline__ float tf32r(float f) {
    unsigned u;
    asm("cvt.rna.tf32.f32 %0, %1;" : "=r"(u) : "f"(f));
    return __uint_as_float(u);
}

__device__ __forceinline__ void mma_tf32(float* c, const unsigned* a, const unsigned* b) {
    asm volatile(
        "mma.sync.aligned.m16n8k8.row.col.f32.tf32.tf32.f32 "
        "{%0,%1,%2,%3}, {%4,%5,%6,%7}, {%8,%9}, {%0,%1,%2,%3};\n"
        : "+f"(c[0]), "+f"(c[1]), "+f"(c[2]), "+f"(c[3])
        : "r"(a[0]), "r"(a[1]), "r"(a[2]), "r"(a[3]), "r"(b[0]), "r"(b[1]));
}

__device__ __forceinline__ uint32_t smem_u32(const void* p) {
    uint32_t a;
    asm("{ .reg .u64 t; cvta.to.shared.u64 t, %1; cvt.u32.u64 %0, t; }"
        : "=r"(a) : "l"(p));
    return a;
}
__device__ __forceinline__ void cpasync16(uint32_t dst, const void* src) {
    asm volatile("cp.async.cg.shared.global [%0], [%1], 16;" :: "r"(dst), "l"(src));
}
#define CP_COMMIT() asm volatile("cp.async.commit_group;" ::: "memory")
#define CP_WAIT0()  asm volatile("cp.async.wait_group 0;" ::: "memory")
#define CP_WAIT1()  asm volatile("cp.async.wait_group 1;" ::: "memory")

// ---------------------------------------------------------------------------
// K0: xn = LayerNorm(x) over C=128.  One warp per row; output tf32-rounded.
// ---------------------------------------------------------------------------
__global__ void k0_ln(const float* __restrict__ x,
                      const float* __restrict__ w,
                      const float* __restrict__ b) {
    int row  = blockIdx.x * blockDim.y + threadIdx.y;
    int lane = threadIdx.x;
    const float* xr = x + (size_t)row * CHN;
    float4 v = *(const float4*)(xr + lane * 4);
    float s = v.x + v.y + v.z + v.w;
    float q = v.x*v.x + v.y*v.y + v.z*v.z + v.w*v.w;
    #pragma unroll
    for (int o = 16; o > 0; o >>= 1) {
        s += __shfl_xor_sync(0xffffffffu, s, o);
        q += __shfl_xor_sync(0xffffffffu, q, o);
    }
    float mean = s * (1.0f / CHN);
    float var  = q * (1.0f / CHN) - mean * mean;
    float rstd = rsqrtf(var + 1e-5f);
    float4 wv = *(const float4*)(w + lane * 4);
    float4 bv = *(const float4*)(b + lane * 4);
    float4 o;
    o.x = tf32r((v.x - mean) * rstd * wv.x + bv.x);
    o.y = tf32r((v.y - mean) * rstd * wv.y + bv.y);
    o.z = tf32r((v.z - mean) * rstd * wv.z + bv.z);
    o.w = tf32r((v.w - mean) * rstd * wv.w + bv.w);
    *(float4*)(g_xn + (size_t)row * CHN + lane * 4) = o;
}

// ---------------------------------------------------------------------------
// K1 (tf32 MMA): unchanged (passing).
// ---------------------------------------------------------------------------
__global__ void __launch_bounds__(256)
k1_proj(const float* __restrict__ pw, const float* __restrict__ gw) {
    __shared__ float sm[(128 + 64 + 64) * 36];
    float* As = sm;             // [128][36]
    float* Ps = sm + 128 * 36;  // [64][36]
    float* Gs = sm + 192 * 36;  // [64][36]

    int tid = threadIdx.x;
    int rowTile = blockIdx.x * 128;
    int chTile  = blockIdx.y * 64;
    int w = tid >> 5, lane = tid & 31;
    int wi = w & 3, wj = w >> 2;
    int gid = lane >> 2, tig = lane & 3;

    float accP[2][4][4] = {}, accG[2][4][4] = {};

    for (int k0 = 0; k0 < CHN; k0 += 32) {
        #pragma unroll
        for (int rep = 0; rep < 4; rep++) {
            int f = tid + rep * 256;
            int k4 = f & 7, r = f >> 3;
            float4 v = *(const float4*)(g_xn + (size_t)(rowTile + r) * CHN + k0 + k4 * 4);
            *(float4*)(As + r * 36 + k4 * 4) = v;
        }
        #pragma unroll
        for (int rep = 0; rep < 2; rep++) {
            int f = tid + rep * 256;
            int k4 = f & 7, c = f >> 3;
            float4 v = *(const float4*)(pw + (size_t)(chTile + c) * CHN + k0 + k4 * 4);
            v.x = tf32r(v.x); v.y = tf32r(v.y); v.z = tf32r(v.z); v.w = tf32r(v.w);
            *(float4*)(Ps + c * 36 + k4 * 4) = v;
            float4 u = *(const float4*)(gw + (size_t)(chTile + c) * CHN + k0 + k4 * 4);
            u.x = tf32r(u.x); u.y = tf32r(u.y); u.z = tf32r(u.z); u.w = tf32r(u.w);
            *(float4*)(Gs + c * 36 + k4 * 4) = u;
        }
        __syncthreads();

        #pragma unroll
        for (int kk = 0; kk < 4; kk++) {
            int kb = kk * 8;
            unsigned a[2][4];
            #pragma unroll
            for (int mi = 0; mi < 2; mi++) {
                int r0 = wi * 32 + mi * 16 + gid;
                a[mi][0] = __float_as_uint(As[r0 * 36 + kb + tig]);
                a[mi][1] = __float_as_uint(As[(r0 + 8) * 36 + kb + tig]);
                a[mi][2] = __float_as_uint(As[r0 * 36 + kb + tig + 4]);
                a[mi][3] = __float_as_uint(As[(r0 + 8) * 36 + kb + tig + 4]);
            }
            #pragma unroll
            for (int nj = 0; nj < 4; nj++) {
                int n0 = wj * 32 + nj * 8 + gid;
                unsigned pb[2], gb[2];
                pb[0] = __float_as_uint(Ps[n0 * 36 + kb + tig]);
                pb[1] = __float_as_uint(Ps[n0 * 36 + kb + tig + 4]);
                gb[0] = __float_as_uint(Gs[n0 * 36 + kb + tig]);
                gb[1] = __float_as_uint(Gs[n0 * 36 + kb + tig + 4]);
                #pragma unroll
                for (int mi = 0; mi < 2; mi++) {
                    mma_tf32(accP[mi][nj], a[mi], pb);
                    mma_tf32(accG[mi][nj], a[mi], gb);
                }
            }
        }
        __syncthreads();
    }

    float* Hs = sm + w * (32 * 33);
    #pragma unroll
    for (int mi = 0; mi < 2; mi++)
        #pragma unroll
        for (int nj = 0; nj < 4; nj++)
            #pragma unroll
            for (int c = 0; c < 4; c++) {
                float h = accP[mi][nj][c] / (1.0f + __expf(-accG[mi][nj][c]));
                int row = mi * 16 + gid + ((c >> 1) << 3);
                int ch  = nj * 8 + tig * 2 + (c & 1);
                Hs[ch * 33 + row] = tf32r(h);
            }
    __syncwarp();
    {
        int chG = chTile + wj * 32 + lane;
        float* dst = (chG < HD) ? (g_a + (size_t)chG * NROWS)
                                : (g_b + (size_t)(chG - HD) * NROWS);
        size_t base = (size_t)rowTile + wi * 32;
        #pragma unroll
        for (int r4 = 0; r4 < 8; r4++) {
            float4 o;
            o.x = Hs[lane * 33 + r4 * 4 + 0];
            o.y = Hs[lane * 33 + r4 * 4 + 1];
            o.z = Hs[lane * 33 + r4 * 4 + 2];
            o.w = Hs[lane * 33 + r4 * 4 + 3];
            *(float4*)(dst + base + r4 * 4) = o;
        }
    }
}

// ---------------------------------------------------------------------------
// K2 (tf32 MMA + cp.async double buffer): t[d][i][j] = sum_k a[d][i][k]*b[d][j][k]
// 128 independent 512x512x512 NT GEMMs. CTA tile 128x128, K staged by 32,
// 2-stage cp.async.cg pipeline in dynamic smem (73.7KB, 2 CTAs/SM).
// ---------------------------------------------------------------------------
#define K2S 36
#define K2_BUF (128 * K2S)                  // floats per matrix per stage
#define K2_SMEM_BYTES (4 * K2_BUF * 4)      // A0,A1,B0,B1 = 73728 B

__global__ void __launch_bounds__(256)
k2_einsum() {
    extern __shared__ float sm2[];
    int tid = threadIdx.x;
    int d = blockIdx.z;
    int iTile = blockIdx.x * 128;
    int jTile = blockIdx.y * 128;
    const float* Ab = g_a + (size_t)d * NROWS;
    const float* Bb = g_b + (size_t)d * NROWS;
    int w = tid >> 5, lane = tid & 31;
    int wi = w & 3, wj = w >> 2;
    int gid = lane >> 2, tig = lane & 3;

    float acc[2][8][4] = {};

    // stage loader: 8 x 16B cp.async per thread (A and B, 4 reps each)
    auto load_stage = [&](int s, int buf) {
        int k0 = s * 32;
        float* Ad = sm2 + buf * K2_BUF;
        float* Bd = sm2 + 2 * K2_BUF + buf * K2_BUF;
        #pragma unroll
        for (int rep = 0; rep < 4; rep++) {
            int f = tid + rep * 256;
            int k4 = f & 7, r = f >> 3;
            cpasync16(smem_u32(Ad + r * K2S + k4 * 4),
                      Ab + (size_t)(iTile + r) * NSEQ + k0 + k4 * 4);
            cpasync16(smem_u32(Bd + r * K2S + k4 * 4),
                      Bb + (size_t)(jTile + r) * NSEQ + k0 + k4 * 4);
        }
    };

    // prologue: prefetch stage 0
    load_stage(0, 0);
    CP_COMMIT();

    for (int s = 0; s < 16; s++) {
        int cur = s & 1;
        if (s + 1 < 16) {
            load_stage(s + 1, 1 - cur);   // overwrites buf used by stage s-1,
            CP_COMMIT();                  // whose consumers finished last iter
            CP_WAIT1();                   // stage s group complete
        } else {
            CP_WAIT0();
        }
        __syncthreads();

        const float* As = sm2 + cur * K2_BUF;
        const float* Bs = sm2 + 2 * K2_BUF + cur * K2_BUF;

        #pragma unroll
        for (int kk = 0; kk < 4; kk++) {
            int kb = kk * 8;
            unsigned a[2][4];
            #pragma unroll
            for (int mi = 0; mi < 2; mi++) {
                int r0 = wi * 32 + mi * 16 + gid;
                a[mi][0] = __float_as_uint(As[r0 * K2S + kb + tig]);
                a[mi][1] = __float_as_uint(As[(r0 + 8) * K2S + kb + tig]);
                a[mi][2] = __float_as_uint(As[r0 * K2S + kb + tig + 4]);
                a[mi][3] = __float_as_uint(As[(r0 + 8) * K2S + kb + tig + 4]);
            }
            #pragma unroll
            for (int nj = 0; nj < 8; nj++) {
                int n0 = wj * 64 + nj * 8 + gid;
                unsigned b[2];
                b[0] = __float_as_uint(Bs[n0 * K2S + kb + tig]);
                b[1] = __float_as_uint(Bs[n0 * K2S + kb + tig + 4]);
                #pragma unroll
                for (int mi = 0; mi < 2; mi++)
                    mma_tf32(acc[mi][nj], a[mi], b);
            }
        }
        __syncthreads();   // all warps done reading buf cur before it is refilled
    }

    float* T = g_t + (size_t)d * NROWS;
    #pragma unroll
    for (int mi = 0; mi < 2; mi++)
        #pragma unroll
        for (int nj = 0; nj < 8; nj++) {
            int r0 = iTile + wi * 32 + mi * 16 + gid;
            int cj = jTile + wj * 64 + nj * 8 + tig * 2;
            float2 v0 = make_float2(acc[mi][nj][0], acc[mi][nj][1]);
            *(float2*)(T + (size_t)r0 * NSEQ + cj) = v0;
            float2 v1 = make_float2(acc[mi][nj][2], acc[mi][nj][3]);
            *(float2*)(T + (size_t)(r0 + 8) * NSEQ + cj) = v1;
        }
}

// ---------------------------------------------------------------------------
// K3a: tn = LayerNorm_d(t), transposing channel-major g_t -> row-major g_tn.
// ---------------------------------------------------------------------------
__global__ void __launch_bounds__(256)
k3a_ln(const float* __restrict__ nw, const float* __restrict__ nb) {
    __shared__ float Ts[64][132];
    __shared__ float red[4][64], red2[4][64];
    __shared__ float mS[64], rS[64];
    int tid = threadIdx.x;
    int e0 = blockIdx.x * 64;

    #pragma unroll
    for (int rep = 0; rep < 32; rep++) {
        int f = tid + rep * 256;
        int e = f & 63;
        int d = f >> 6;
        Ts[e][d] = g_t[(size_t)d * NROWS + e0 + e];
    }
    __syncthreads();

    {
        int e = tid & 63;
        int dc = tid >> 6;
        float s = 0.f, q = 0.f;
        #pragma unroll
        for (int u4 = 0; u4 < 8; u4++) {
            float4 v = *(const float4*)&Ts[e][dc * 32 + u4 * 4];
            s += v.x + v.y + v.z + v.w;
            q += v.x*v.x + v.y*v.y + v.z*v.z + v.w*v.w;
        }
        red[dc][e] = s;
        red2[dc][e] = q;
    }
    __syncthreads();
    if (tid < 64) {
        float s = red[0][tid] + red[1][tid] + red[2][tid] + red[3][tid];
        float q = red2[0][tid] + red2[1][tid] + red2[2][tid] + red2[3][tid];
        float mean = s * (1.0f / HD);
        float var  = q * (1.0f / HD) - mean * mean;
        mS[tid] = mean;
        rS[tid] = rsqrtf(var + 1e-5f);
    }
    __syncthreads();

    {
        int d4 = tid & 31;
        float4 wv = *(const float4*)(nw + d4 * 4);
        float4 bv = *(const float4*)(nb + d4 * 4);
        #pragma unroll
        for (int rep = 0; rep < 8; rep++) {
            int e = (tid >> 5) + rep * 8;
            float mean = mS[e], rstd = rS[e];
            float4 v = *(const float4*)&Ts[e][d4 * 4];
            float4 o;
            o.x = tf32r((v.x - mean) * rstd * wv.x + bv.x);
            o.y = tf32r((v.y - mean) * rstd * wv.y + bv.y);
            o.z = tf32r((v.z - mean) * rstd * wv.z + bv.z);
            o.w = tf32r((v.w - mean) * rstd * wv.w + bv.w);
            *(float4*)(g_tn + (size_t)(e0 + e) * HD + d4 * 4) = o;
        }
    }
}

// ---------------------------------------------------------------------------
// K3b (tf32 MMA): unchanged (passing). K staged by 16, stride 20.
// ---------------------------------------------------------------------------
#define K3_STRIDE 20
__global__ void __launch_bounds__(256)
k3b_out(const float* __restrict__ powt, const float* __restrict__ gowt,
        float* __restrict__ out) {
    __shared__ float sm[(128 + 128 + 64 + 64) * K3_STRIDE];
    float* As = sm;
    float* Xs = sm + 128 * K3_STRIDE;
    float* Ps = sm + 256 * K3_STRIDE;
    float* Gs = sm + 320 * K3_STRIDE;

    int tid = threadIdx.x;
    int rowTile = blockIdx.x * 128;
    int chTile  = blockIdx.y * 64;
    int w = tid >> 5, lane = tid & 31;
    int wi = w & 3, wj = w >> 2;
    int gid = lane >> 2, tig = lane & 3;

    float accO[2][4][4] = {}, accG[2][4][4] = {};

    for (int k0 = 0; k0 < HD; k0 += 16) {
        #pragma unroll
        for (int rep = 0; rep < 2; rep++) {
            int f = tid + rep * 256;
            int k4 = f & 3, r = f >> 2;
            float4 v = *(const float4*)(g_tn + (size_t)(rowTile + r) * HD + k0 + k4 * 4);
            *(float4*)(As + r * K3_STRIDE + k4 * 4) = v;
            float4 u = *(const float4*)(g_xn + (size_t)(rowTile + r) * CHN + k0 + k4 * 4);
            *(float4*)(Xs + r * K3_STRIDE + k4 * 4) = u;
        }
        {
            int f = tid;
            int k4 = f & 3, c = f >> 2;
            float4 v = *(const float4*)(powt + (size_t)(chTile + c) * HD + k0 + k4 * 4);
            v.x = tf32r(v.x); v.y = tf32r(v.y); v.z = tf32r(v.z); v.w = tf32r(v.w);
            *(float4*)(Ps + c * K3_STRIDE + k4 * 4) = v;
            float4 u = *(const float4*)(gowt + (size_t)(chTile + c) * CHN + k0 + k4 * 4);
            u.x = tf32r(u.x); u.y = tf32r(u.y); u.z = tf32r(u.z); u.w = tf32r(u.w);
            *(float4*)(Gs + c * K3_STRIDE + k4 * 4) = u;
        }
        __syncthreads();

        #pragma unroll
        for (int kk = 0; kk < 2; kk++) {
            int kb = kk * 8;
            unsigned a[2][4], x[2][4];
            #pragma unroll
            for (int mi = 0; mi < 2; mi++) {
                int r0 = wi * 32 + mi * 16 + gid;
                a[mi][0] = __float_as_uint(As[r0 * K3_STRIDE + kb + tig]);
                a[mi][1] = __float_as_uint(As[(r0 + 8) * K3_STRIDE + kb + tig]);
                a[mi][2] = __float_as_uint(As[r0 * K3_STRIDE + kb + tig + 4]);
                a[mi][3] = __float_as_uint(As[(r0 + 8) * K3_STRIDE + kb + tig + 4]);
                x[mi][0] = __float_as_uint(Xs[r0 * K3_STRIDE + kb + tig]);
                x[mi][1] = __float_as_uint(Xs[(r0 + 8) * K3_STRIDE + kb + tig]);
                x[mi][2] = __float_as_uint(Xs[r0 * K3_STRIDE + kb + tig + 4]);
                x[mi][3] = __float_as_uint(Xs[(r0 + 8) * K3_STRIDE + kb + tig + 4]);
            }
            #pragma unroll
            for (int nj = 0; nj < 4; nj++) {
                int n0 = wj * 32 + nj * 8 + gid;
                unsigned pb[2], gb[2];
                pb[0] = __float_as_uint(Ps[n0 * K3_STRIDE + kb + tig]);
                pb[1] = __float_as_uint(Ps[n0 * K3_STRIDE + kb + tig + 4]);
                gb[0] = __float_as_uint(Gs[n0 * K3_STRIDE + kb + tig]);
                gb[1] = __float_as_uint(Gs[n0 * K3_STRIDE + kb + tig + 4]);
                #pragma unroll
                for (int mi = 0; mi < 2; mi++) {
                    mma_tf32(accO[mi][nj], a[mi], pb);
                    mma_tf32(accG[mi][nj], x[mi], gb);
                }
            }
        }
        __syncthreads();
    }

    #pragma unroll
    for (int mi = 0; mi < 2; mi++)
        #pragma unroll
        for (int nj = 0; nj < 4; nj++) {
            int r0 = rowTile + wi * 32 + mi * 16 + gid;
            int cj = chTile + wj * 32 + nj * 8 + tig * 2;
            float2 v0;
            v0.x = accO[mi][nj][0] / (1.0f + __expf(-accG[mi][nj][0]));
            v0.y = accO[mi][nj][1] / (1.0f + __expf(-accG[mi][nj][1]));
            *(float2*)(out + (size_t)r0 * CHN + cj) = v0;
            float2 v1;
            v1.x = accO[mi][nj][2] / (1.0f + __expf(-accG[mi][nj][2]));
            v1.y = accO[mi][nj][3] / (1.0f + __expf(-accG[mi][nj][3]));
            *(float2*)(out + (size_t)(r0 + 8) * CHN + cj) = v1;
        }
}

// ---------------------------------------------------------------------------
extern "C" void kernel_launch(void* const* d_in, const int* in_sizes, int n_in,
                              void* d_out, int out_size) {
    const float* x       = (const float*)d_in[0];
    const float* nin_w   = (const float*)d_in[1];
    const float* nin_b   = (const float*)d_in[2];
    const float* p_in_w  = (const float*)d_in[3];
    const float* g_in_w  = (const float*)d_in[4];
    const float* nout_w  = (const float*)d_in[5];
    const float* nout_b  = (const float*)d_in[6];
    const float* p_out_w = (const float*)d_in[7];
    const float* g_out_w = (const float*)d_in[8];
    float* out = (float*)d_out;

    cudaFuncSetAttribute(k2_einsum,
                         cudaFuncAttributeMaxDynamicSharedMemorySize, K2_SMEM_BYTES);

    k0_ln    <<<NROWS / 8, dim3(32, 8)>>>(x, nin_w, nin_b);
    k1_proj  <<<dim3(NROWS / 128, 4), 256>>>(p_in_w, g_in_w);
    k2_einsum<<<dim3(4, 4, 128), 256, K2_SMEM_BYTES>>>();
    k3a_ln   <<<NROWS / 64, 256>>>(nout_w, nout_b);
    k3b_out  <<<dim3(NROWS / 128, 2), 256>>>(p_out_w, g_out_w, out);
}

// round 9
// speedup vs baseline: 4.0336x; 1.1269x over previous
#include <cuda_runtime.h>
#include <math.h>
#include <stdint.h>

#define NSEQ 512
#define CHN  128
#define HD   128
#define NROWS (NSEQ*NSEQ)   // 262144

// Scratch (__device__ globals: allocation-free per harness rules)
__device__ float g_xn[(size_t)NROWS * CHN];   // LN(x) row-major [row][c]  (tf32-rounded)
__device__ float g_a [(size_t)HD * NROWS];    // channel-major [d][i*512+k] (tf32-rounded)
__device__ float g_b [(size_t)HD * NROWS];    // channel-major [d][j*512+k] (tf32-rounded)
__device__ float g_t [(size_t)HD * NROWS];    // channel-major [d][i*512+j] (fp32)
__device__ float g_tn[(size_t)NROWS * HD];    // LN_d(t) row-major [e][d]   (tf32-rounded)
__device__ float g_wr[98304];                 // tf32-rounded weights:
                                              // [0,32768) p_in, [32768,65536) g_in,
                                              // [65536,81920) p_out, [81920,98304) g_out

// ---------------------------------------------------------------------------
// helpers
// ---------------------------------------------------------------------------
__device__ __forceinline__ float tf32r(float f) {
    unsigned u;
    asm("cvt.rna.tf32.f32 %0, %1;" : "=r"(u) : "f"(f));
    return __uint_as_float(u);
}

__device__ __forceinline__ void mma_tf32(float* c, const unsigned* a, const unsigned* b) {
    asm volatile(
        "mma.sync.aligned.m16n8k8.row.col.f32.tf32.tf32.f32 "
        "{%0,%1,%2,%3}, {%4,%5,%6,%7}, {%8,%9}, {%0,%1,%2,%3};\n"
        : "+f"(c[0]), "+f"(c[1]), "+f"(c[2]), "+f"(c[3])
        : "r"(a[0]), "r"(a[1]), "r"(a[2]), "r"(a[3]), "r"(b[0]), "r"(b[1]));
}

__device__ __forceinline__ uint32_t smem_u32(const void* p) {
    uint32_t a;
    asm("{ .reg .u64 t; cvta.to.shared.u64 t, %1; cvt.u32.u64 %0, t; }"
        : "=r"(a) : "l"(p));
    return a;
}
__device__ __forceinline__ void cpasync16(uint32_t dst, const void* src) {
    asm volatile("cp.async.cg.shared.global [%0], [%1], 16;" :: "r"(dst), "l"(src));
}
#define CP_COMMIT() asm volatile("cp.async.commit_group;" ::: "memory")
#define CP_WAIT0()  asm volatile("cp.async.wait_group 0;" ::: "memory")
#define CP_WAIT1()  asm volatile("cp.async.wait_group 1;" ::: "memory")

// ---------------------------------------------------------------------------
// KP: tf32-round all weight matrices once into g_wr (bit-identical to the
// previous per-tile rounding; enables cp.async weight loads downstream).
// ---------------------------------------------------------------------------
__global__ void kprep(const float* __restrict__ pw, const float* __restrict__ gw,
                      const float* __restrict__ po, const float* __restrict__ go) {
    int i = blockIdx.x * 256 + threadIdx.x;        // grid covers 98304
    if (i < 32768)        g_wr[i] = tf32r(pw[i]);
    else if (i < 65536)   g_wr[i] = tf32r(gw[i - 32768]);
    else if (i < 81920)   g_wr[i] = tf32r(po[i - 65536]);
    else                  g_wr[i] = tf32r(go[i - 81920]);
}

// ---------------------------------------------------------------------------
// K0: xn = LayerNorm(x) over C=128.  One warp per row; output tf32-rounded.
// ---------------------------------------------------------------------------
__global__ void k0_ln(const float* __restrict__ x,
                      const float* __restrict__ w,
                      const float* __restrict__ b) {
    int row  = blockIdx.x * blockDim.y + threadIdx.y;
    int lane = threadIdx.x;
    const float* xr = x + (size_t)row * CHN;
    float4 v = *(const float4*)(xr + lane * 4);
    float s = v.x + v.y + v.z + v.w;
    float q = v.x*v.x + v.y*v.y + v.z*v.z + v.w*v.w;
    #pragma unroll
    for (int o = 16; o > 0; o >>= 1) {
        s += __shfl_xor_sync(0xffffffffu, s, o);
        q += __shfl_xor_sync(0xffffffffu, q, o);
    }
    float mean = s * (1.0f / CHN);
    float var  = q * (1.0f / CHN) - mean * mean;
    float rstd = rsqrtf(var + 1e-5f);
    float4 wv = *(const float4*)(w + lane * 4);
    float4 bv = *(const float4*)(b + lane * 4);
    float4 o;
    o.x = tf32r((v.x - mean) * rstd * wv.x + bv.x);
    o.y = tf32r((v.y - mean) * rstd * wv.y + bv.y);
    o.z = tf32r((v.z - mean) * rstd * wv.z + bv.z);
    o.w = tf32r((v.w - mean) * rstd * wv.w + bv.w);
    *(float4*)(g_xn + (size_t)row * CHN + lane * 4) = o;
}

// ---------------------------------------------------------------------------
// K1 (tf32 MMA + cp.async double buffer): h = (xn@p^T)*sigmoid(xn@g^T)
// CTA 128 rows x 64 ch, K=128 in 4 stages of 32, all loads via cp.async from
// pre-rounded g_xn / g_wr. Epilogue unchanged.
// ---------------------------------------------------------------------------
#define K1S 36
#define K1_ABUF (128 * K1S)
#define K1_WBUF (64 * K1S)
#define K1_STAGE (K1_ABUF + 2 * K1_WBUF)
#define K1_SMEM_BYTES (2 * K1_STAGE * 4)    // 73728

__global__ void __launch_bounds__(256)
k1_proj() {
    extern __shared__ float sm1[];
    int tid = threadIdx.x;
    int rowTile = blockIdx.x * 128;
    int chTile  = blockIdx.y * 64;
    const float* wp = g_wr;
    const float* wg = g_wr + 32768;
    int w = tid >> 5, lane = tid & 31;
    int wi = w & 3, wj = w >> 2;
    int gid = lane >> 2, tig = lane & 3;

    float accP[2][4][4] = {}, accG[2][4][4] = {};

    auto load_stage = [&](int s, int buf) {
        int k0 = s * 32;
        float* As = sm1 + buf * K1_STAGE;
        float* Ps = As + K1_ABUF;
        float* Gs = Ps + K1_WBUF;
        #pragma unroll
        for (int rep = 0; rep < 4; rep++) {
            int f = tid + rep * 256;          // 0..1023
            int k4 = f & 7, r = f >> 3;
            cpasync16(smem_u32(As + r * K1S + k4 * 4),
                      g_xn + (size_t)(rowTile + r) * CHN + k0 + k4 * 4);
        }
        #pragma unroll
        for (int rep = 0; rep < 2; rep++) {
            int f = tid + rep * 256;          // 0..511
            int k4 = f & 7, c = f >> 3;
            cpasync16(smem_u32(Ps + c * K1S + k4 * 4),
                      wp + (size_t)(chTile + c) * CHN + k0 + k4 * 4);
            cpasync16(smem_u32(Gs + c * K1S + k4 * 4),
                      wg + (size_t)(chTile + c) * CHN + k0 + k4 * 4);
        }
    };

    load_stage(0, 0);
    CP_COMMIT();

    for (int s = 0; s < 4; s++) {
        int cur = s & 1;
        if (s + 1 < 4) {
            load_stage(s + 1, 1 - cur);
            CP_COMMIT();
            CP_WAIT1();
        } else {
            CP_WAIT0();
        }
        __syncthreads();

        const float* As = sm1 + cur * K1_STAGE;
        const float* Ps = As + K1_ABUF;
        const float* Gs = Ps + K1_WBUF;

        #pragma unroll
        for (int kk = 0; kk < 4; kk++) {
            int kb = kk * 8;
            unsigned a[2][4];
            #pragma unroll
            for (int mi = 0; mi < 2; mi++) {
                int r0 = wi * 32 + mi * 16 + gid;
                a[mi][0] = __float_as_uint(As[r0 * K1S + kb + tig]);
                a[mi][1] = __float_as_uint(As[(r0 + 8) * K1S + kb + tig]);
                a[mi][2] = __float_as_uint(As[r0 * K1S + kb + tig + 4]);
                a[mi][3] = __float_as_uint(As[(r0 + 8) * K1S + kb + tig + 4]);
            }
            #pragma unroll
            for (int nj = 0; nj < 4; nj++) {
                int n0 = wj * 32 + nj * 8 + gid;
                unsigned pb[2], gb[2];
                pb[0] = __float_as_uint(Ps[n0 * K1S + kb + tig]);
                pb[1] = __float_as_uint(Ps[n0 * K1S + kb + tig + 4]);
                gb[0] = __float_as_uint(Gs[n0 * K1S + kb + tig]);
                gb[1] = __float_as_uint(Gs[n0 * K1S + kb + tig + 4]);
                #pragma unroll
                for (int mi = 0; mi < 2; mi++) {
                    mma_tf32(accP[mi][nj], a[mi], pb);
                    mma_tf32(accG[mi][nj], a[mi], gb);
                }
            }
        }
        __syncthreads();
    }

    // epilogue: h = P * sigmoid(G); per-warp smem transpose -> channel-major
    float* Hs = sm1 + w * (32 * 33);
    #pragma unroll
    for (int mi = 0; mi < 2; mi++)
        #pragma unroll
        for (int nj = 0; nj < 4; nj++)
            #pragma unroll
            for (int c = 0; c < 4; c++) {
                float h = accP[mi][nj][c] / (1.0f + __expf(-accG[mi][nj][c]));
                int row = mi * 16 + gid + ((c >> 1) << 3);
                int ch  = nj * 8 + tig * 2 + (c & 1);
                Hs[ch * 33 + row] = tf32r(h);
            }
    __syncwarp();
    {
        int chG = chTile + wj * 32 + lane;
        float* dst = (chG < HD) ? (g_a + (size_t)chG * NROWS)
                                : (g_b + (size_t)(chG - HD) * NROWS);
        size_t base = (size_t)rowTile + wi * 32;
        #pragma unroll
        for (int r4 = 0; r4 < 8; r4++) {
            float4 o;
            o.x = Hs[lane * 33 + r4 * 4 + 0];
            o.y = Hs[lane * 33 + r4 * 4 + 1];
            o.z = Hs[lane * 33 + r4 * 4 + 2];
            o.w = Hs[lane * 33 + r4 * 4 + 3];
            *(float4*)(dst + base + r4 * 4) = o;
        }
    }
}

// ---------------------------------------------------------------------------
// K2 (tf32 MMA + cp.async double buffer): unchanged from round 8 (passing).
// ---------------------------------------------------------------------------
#define K2S 36
#define K2_BUF (128 * K2S)
#define K2_SMEM_BYTES (4 * K2_BUF * 4)      // 73728

__global__ void __launch_bounds__(256)
k2_einsum() {
    extern __shared__ float sm2[];
    int tid = threadIdx.x;
    int d = blockIdx.z;
    int iTile = blockIdx.x * 128;
    int jTile = blockIdx.y * 128;
    const float* Ab = g_a + (size_t)d * NROWS;
    const float* Bb = g_b + (size_t)d * NROWS;
    int w = tid >> 5, lane = tid & 31;
    int wi = w & 3, wj = w >> 2;
    int gid = lane >> 2, tig = lane & 3;

    float acc[2][8][4] = {};

    auto load_stage = [&](int s, int buf) {
        int k0 = s * 32;
        float* Ad = sm2 + buf * K2_BUF;
        float* Bd = sm2 + 2 * K2_BUF + buf * K2_BUF;
        #pragma unroll
        for (int rep = 0; rep < 4; rep++) {
            int f = tid + rep * 256;
            int k4 = f & 7, r = f >> 3;
            cpasync16(smem_u32(Ad + r * K2S + k4 * 4),
                      Ab + (size_t)(iTile + r) * NSEQ + k0 + k4 * 4);
            cpasync16(smem_u32(Bd + r * K2S + k4 * 4),
                      Bb + (size_t)(jTile + r) * NSEQ + k0 + k4 * 4);
        }
    };

    load_stage(0, 0);
    CP_COMMIT();

    for (int s = 0; s < 16; s++) {
        int cur = s & 1;
        if (s + 1 < 16) {
            load_stage(s + 1, 1 - cur);
            CP_COMMIT();
            CP_WAIT1();
        } else {
            CP_WAIT0();
        }
        __syncthreads();

        const float* As = sm2 + cur * K2_BUF;
        const float* Bs = sm2 + 2 * K2_BUF + cur * K2_BUF;

        #pragma unroll
        for (int kk = 0; kk < 4; kk++) {
            int kb = kk * 8;
            unsigned a[2][4];
            #pragma unroll
            for (int mi = 0; mi < 2; mi++) {
                int r0 = wi * 32 + mi * 16 + gid;
                a[mi][0] = __float_as_uint(As[r0 * K2S + kb + tig]);
                a[mi][1] = __float_as_uint(As[(r0 + 8) * K2S + kb + tig]);
                a[mi][2] = __float_as_uint(As[r0 * K2S + kb + tig + 4]);
                a[mi][3] = __float_as_uint(As[(r0 + 8) * K2S + kb + tig + 4]);
            }
            #pragma unroll
            for (int nj = 0; nj < 8; nj++) {
                int n0 = wj * 64 + nj * 8 + gid;
                unsigned b[2];
                b[0] = __float_as_uint(Bs[n0 * K2S + kb + tig]);
                b[1] = __float_as_uint(Bs[n0 * K2S + kb + tig + 4]);
                #pragma unroll
                for (int mi = 0; mi < 2; mi++)
                    mma_tf32(acc[mi][nj], a[mi], b);
            }
        }
        __syncthreads();
    }

    float* T = g_t + (size_t)d * NROWS;
    #pragma unroll
    for (int mi = 0; mi < 2; mi++)
        #pragma unroll
        for (int nj = 0; nj < 8; nj++) {
            int r0 = iTile + wi * 32 + mi * 16 + gid;
            int cj = jTile + wj * 64 + nj * 8 + tig * 2;
            float2 v0 = make_float2(acc[mi][nj][0], acc[mi][nj][1]);
            *(float2*)(T + (size_t)r0 * NSEQ + cj) = v0;
            float2 v1 = make_float2(acc[mi][nj][2], acc[mi][nj][3]);
            *(float2*)(T + (size_t)(r0 + 8) * NSEQ + cj) = v1;
        }
}

// ---------------------------------------------------------------------------
// K3a: tn = LayerNorm_d(t): unchanged (at memory floor).
// ---------------------------------------------------------------------------
__global__ void __launch_bounds__(256)
k3a_ln(const float* __restrict__ nw, const float* __restrict__ nb) {
    __shared__ float Ts[64][132];
    __shared__ float red[4][64], red2[4][64];
    __shared__ float mS[64], rS[64];
    int tid = threadIdx.x;
    int e0 = blockIdx.x * 64;

    #pragma unroll
    for (int rep = 0; rep < 32; rep++) {
        int f = tid + rep * 256;
        int e = f & 63;
        int d = f >> 6;
        Ts[e][d] = g_t[(size_t)d * NROWS + e0 + e];
    }
    __syncthreads();

    {
        int e = tid & 63;
        int dc = tid >> 6;
        float s = 0.f, q = 0.f;
        #pragma unroll
        for (int u4 = 0; u4 < 8; u4++) {
            float4 v = *(const float4*)&Ts[e][dc * 32 + u4 * 4];
            s += v.x + v.y + v.z + v.w;
            q += v.x*v.x + v.y*v.y + v.z*v.z + v.w*v.w;
        }
        red[dc][e] = s;
        red2[dc][e] = q;
    }
    __syncthreads();
    if (tid < 64) {
        float s = red[0][tid] + red[1][tid] + red[2][tid] + red[3][tid];
        float q = red2[0][tid] + red2[1][tid] + red2[2][tid] + red2[3][tid];
        float mean = s * (1.0f / HD);
        float var  = q * (1.0f / HD) - mean * mean;
        mS[tid] = mean;
        rS[tid] = rsqrtf(var + 1e-5f);
    }
    __syncthreads();

    {
        int d4 = tid & 31;
        float4 wv = *(const float4*)(nw + d4 * 4);
        float4 bv = *(const float4*)(nb + d4 * 4);
        #pragma unroll
        for (int rep = 0; rep < 8; rep++) {
            int e = (tid >> 5) + rep * 8;
            float mean = mS[e], rstd = rS[e];
            float4 v = *(const float4*)&Ts[e][d4 * 4];
            float4 o;
            o.x = tf32r((v.x - mean) * rstd * wv.x + bv.x);
            o.y = tf32r((v.y - mean) * rstd * wv.y + bv.y);
            o.z = tf32r((v.z - mean) * rstd * wv.z + bv.z);
            o.w = tf32r((v.w - mean) * rstd * wv.w + bv.w);
            *(float4*)(g_tn + (size_t)(e0 + e) * HD + d4 * 4) = o;
        }
    }
}

// ---------------------------------------------------------------------------
// K3b (tf32 MMA + cp.async double buffer): out = (tn@p_out^T)*sigmoid(xn@g_out^T)
// K=128 in 8 stages of 16; all loads via cp.async from pre-rounded sources.
// ---------------------------------------------------------------------------
#define K3S 20
#define K3_ABUF (128 * K3S)
#define K3_WBUF (64 * K3S)
#define K3_STAGE (2 * K3_ABUF + 2 * K3_WBUF)
#define K3_SMEM_BYTES (2 * K3_STAGE * 4)    // 61440

__global__ void __launch_bounds__(256)
k3b_out(float* __restrict__ out) {
    extern __shared__ float sm3[];
    int tid = threadIdx.x;
    int rowTile = blockIdx.x * 128;
    int chTile  = blockIdx.y * 64;
    const float* powt = g_wr + 65536;
    const float* gowt = g_wr + 81920;
    int w = tid >> 5, lane = tid & 31;
    int wi = w & 3, wj = w >> 2;
    int gid = lane >> 2, tig = lane & 3;

    float accO[2][4][4] = {}, accG[2][4][4] = {};

    auto load_stage = [&](int s, int buf) {
        int k0 = s * 16;
        float* As = sm3 + buf * K3_STAGE;
        float* Xs = As + K3_ABUF;
        float* Ps = Xs + K3_ABUF;
        float* Gs = Ps + K3_WBUF;
        #pragma unroll
        for (int rep = 0; rep < 2; rep++) {
            int f = tid + rep * 256;          // 0..511
            int k4 = f & 3, r = f >> 2;       // r 0..127
            cpasync16(smem_u32(As + r * K3S + k4 * 4),
                      g_tn + (size_t)(rowTile + r) * HD + k0 + k4 * 4);
            cpasync16(smem_u32(Xs + r * K3S + k4 * 4),
                      g_xn + (size_t)(rowTile + r) * CHN + k0 + k4 * 4);
        }
        {
            int f = tid;                      // 0..255
            int k4 = f & 3, c = f >> 2;       // c 0..63
            cpasync16(smem_u32(Ps + c * K3S + k4 * 4),
                      powt + (size_t)(chTile + c) * HD + k0 + k4 * 4);
            cpasync16(smem_u32(Gs + c * K3S + k4 * 4),
                      gowt + (size_t)(chTile + c) * CHN + k0 + k4 * 4);
        }
    };

    load_stage(0, 0);
    CP_COMMIT();

    for (int s = 0; s < 8; s++) {
        int cur = s & 1;
        if (s + 1 < 8) {
            load_stage(s + 1, 1 - cur);
            CP_COMMIT();
            CP_WAIT1();
        } else {
            CP_WAIT0();
        }
        __syncthreads();

        const float* As = sm3 + cur * K3_STAGE;
        const float* Xs = As + K3_ABUF;
        const float* Ps = Xs + K3_ABUF;
        const float* Gs = Ps + K3_WBUF;

        #pragma unroll
        for (int kk = 0; kk < 2; kk++) {
            int kb = kk * 8;
            unsigned a[2][4], x[2][4];
            #pragma unroll
            for (int mi = 0; mi < 2; mi++) {
                int r0 = wi * 32 + mi * 16 + gid;
                a[mi][0] = __float_as_uint(As[r0 * K3S + kb + tig]);
                a[mi][1] = __float_as_uint(As[(r0 + 8) * K3S + kb + tig]);
                a[mi][2] = __float_as_uint(As[r0 * K3S + kb + tig + 4]);
                a[mi][3] = __float_as_uint(As[(r0 + 8) * K3S + kb + tig + 4]);
                x[mi][0] = __float_as_uint(Xs[r0 * K3S + kb + tig]);
                x[mi][1] = __float_as_uint(Xs[(r0 + 8) * K3S + kb + tig]);
                x[mi][2] = __float_as_uint(Xs[r0 * K3S + kb + tig + 4]);
                x[mi][3] = __float_as_uint(Xs[(r0 + 8) * K3S + kb + tig + 4]);
            }
            #pragma unroll
            for (int nj = 0; nj < 4; nj++) {
                int n0 = wj * 32 + nj * 8 + gid;
                unsigned pb[2], gb[2];
                pb[0] = __float_as_uint(Ps[n0 * K3S + kb + tig]);
                pb[1] = __float_as_uint(Ps[n0 * K3S + kb + tig + 4]);
                gb[0] = __float_as_uint(Gs[n0 * K3S + kb + tig]);
                gb[1] = __float_as_uint(Gs[n0 * K3S + kb + tig + 4]);
                #pragma unroll
                for (int mi = 0; mi < 2; mi++) {
                    mma_tf32(accO[mi][nj], a[mi], pb);
                    mma_tf32(accG[mi][nj], x[mi], gb);
                }
            }
        }
        __syncthreads();
    }

    #pragma unroll
    for (int mi = 0; mi < 2; mi++)
        #pragma unroll
        for (int nj = 0; nj < 4; nj++) {
            int r0 = rowTile + wi * 32 + mi * 16 + gid;
            int cj = chTile + wj * 32 + nj * 8 + tig * 2;
            float2 v0;
            v0.x = accO[mi][nj][0] / (1.0f + __expf(-accG[mi][nj][0]));
            v0.y = accO[mi][nj][1] / (1.0f + __expf(-accG[mi][nj][1]));
            *(float2*)(out + (size_t)r0 * CHN + cj) = v0;
            float2 v1;
            v1.x = accO[mi][nj][2] / (1.0f + __expf(-accG[mi][nj][2]));
            v1.y = accO[mi][nj][3] / (1.0f + __expf(-accG[mi][nj][3]));
            *(float2*)(out + (size_t)(r0 + 8) * CHN + cj) = v1;
        }
}

// ---------------------------------------------------------------------------
extern "C" void kernel_launch(void* const* d_in, const int* in_sizes, int n_in,
                              void* d_out, int out_size) {
    const float* x       = (const float*)d_in[0];
    const float* nin_w   = (const float*)d_in[1];
    const float* nin_b   = (const float*)d_in[2];
    const float* p_in_w  = (const float*)d_in[3];
    const float* g_in_w  = (const float*)d_in[4];
    const float* nout_w  = (const float*)d_in[5];
    const float* nout_b  = (const float*)d_in[6];
    const float* p_out_w = (const float*)d_in[7];
    const float* g_out_w = (const float*)d_in[8];
    float* out = (float*)d_out;

    cudaFuncSetAttribute(k1_proj,
                         cudaFuncAttributeMaxDynamicSharedMemorySize, K1_SMEM_BYTES);
    cudaFuncSetAttribute(k2_einsum,
                         cudaFuncAttributeMaxDynamicSharedMemorySize, K2_SMEM_BYTES);
    cudaFuncSetAttribute(k3b_out,
                         cudaFuncAttributeMaxDynamicSharedMemorySize, K3_SMEM_BYTES);

    kprep    <<<384, 256>>>(p_in_w, g_in_w, p_out_w, g_out_w);
    k0_ln    <<<NROWS / 8, dim3(32, 8)>>>(x, nin_w, nin_b);
    k1_proj  <<<dim3(NROWS / 128, 4), 256, K1_SMEM_BYTES>>>();
    k2_einsum<<<dim3(4, 4, 128), 256, K2_SMEM_BYTES>>>();
    k3a_ln   <<<NROWS / 64, 256>>>(nout_w, nout_b);
    k3b_out  <<<dim3(NROWS / 128, 2), 256, K3_SMEM_BYTES>>>(out);
}